// round 2
// baseline (speedup 1.0000x reference)
#include <cuda_runtime.h>
#include <cuda_bf16.h>
#include <math.h>

// Problem constants
#define Bc   4
#define Tc   512
#define Fc   32
#define Dc   128
#define NHc  4
#define HDc  32
#define WINc 64
#define HIDc 512
#define Sc   (Bc*Fc)          // 128 sequences
#define ROWS (Sc*Tc)          // 65536 rows

// ---------------- scratch (device globals; no allocation) ----------------
// Buffer reuse: g_qk doubles as h3 (qk dead after QK GEMM);
//               g_h1 doubles as y  (h1 dead after V GEMM).
__device__ float g_hcf[ROWS*Dc];
__device__ float g_h1 [ROWS*Dc];     // h1, later y
__device__ float g_qk [ROWS*Dc];     // qk (roped), later h3
__device__ float g_QK [ROWS*2*Dc];   // cols 0..127 = Q, 128..255 = K
__device__ float g_V  [ROWS*Dc];
__device__ float g_O  [ROWS*Dc];
__device__ float g_g  [ROWS*HIDc];
__device__ float g_ysum[ROWS];

// ---------------- block reduce (128 threads, 4 warps) ----------------
__device__ __forceinline__ float block_reduce_sum128(float v, float* sbuf) {
    int lane = threadIdx.x & 31, w = threadIdx.x >> 5;
    #pragma unroll
    for (int o = 16; o; o >>= 1) v += __shfl_xor_sync(0xffffffffu, v, o);
    if (lane == 0) sbuf[w] = v;
    __syncthreads();
    float r = 0.f;
    if (w == 0) {
        r = (lane < 4) ? sbuf[lane] : 0.f;
        #pragma unroll
        for (int o = 2; o; o >>= 1) r += __shfl_xor_sync(0xffffffffu, r, o);
        if (lane == 0) sbuf[0] = r;
    }
    __syncthreads();
    r = sbuf[0];
    __syncthreads();
    return r;
}

// ---------------- K1: hcf (outer product) + LN1 + RoPE ----------------
__global__ void k1_hcf_ln_rope(const float* __restrict__ x,
                               const float* __restrict__ W_in,
                               const float* __restrict__ b_in,
                               const float* __restrict__ gamma1,
                               const float* __restrict__ beta1) {
    __shared__ float sbuf[4];
    int row = blockIdx.x;              // s*T + t
    int d   = threadIdx.x;             // 0..127
    int s = row >> 9, t = row & (Tc-1);
    int b = s >> 5, f = s & (Fc-1);

    float hv = x[(b*Tc + t)*Fc + f] * W_in[d*Fc + f] + b_in[d];

    float mean = block_reduce_sum128(hv, sbuf) * (1.f/Dc);
    float dv = hv - mean;
    float var = block_reduce_sum128(dv*dv, sbuf) * (1.f/Dc);
    float h1v = dv * rsqrtf(var + 1e-5f) * gamma1[d] + beta1[d];

    g_hcf[row*Dc + d] = hv;
    g_h1 [row*Dc + d] = h1v;

    // RoPE (per head of 32; even/odd interleaved pairs are adjacent lanes)
    float part = __shfl_xor_sync(0xffffffffu, h1v, 1);
    int hd = d & (HDc-1);
    int i2 = hd >> 1;
    float inv = expf(-(float)(2*i2) * (9.210340371976184f / (float)HDc));
    float fr  = (float)t * inv;
    float sn = sinf(fr), cs = cosf(fr);
    float qv = ((d & 1) == 0) ? (h1v*cs - part*sn) : (part*sn + h1v*cs);
    g_qk[row*Dc + d] = qv;
}

// ---------------- GEMM: C[M,N] = A[M,K] @ B[N,K]^T + bias ----------------
// EPI 0: C = acc+bias ; EPI 1: gelu(acc+bias) ; EPI 2: rowsum(acc+bias) -> atomicAdd rowsum[], no C
#define BM 64
#define BN 64
#define BK 16
template<int EPI>
__global__ __launch_bounds__(256) void gemm_nt(const float* __restrict__ A,
                                               const float* __restrict__ B,
                                               const float* __restrict__ bias,
                                               float* __restrict__ C,
                                               int M, int N, int K,
                                               float* __restrict__ rowsum) {
    __shared__ float As[BM][BK+4];
    __shared__ float Bs[BN][BK+4];
    int bm = blockIdx.y * BM;
    int bn = blockIdx.x * BN;
    int tid = threadIdx.x;
    int tx = tid & 15, ty = tid >> 4;
    int lrow = tid >> 2, lcol = (tid & 3) * 4;

    float acc[4][4];
    #pragma unroll
    for (int i=0;i<4;i++)
        #pragma unroll
        for (int j=0;j<4;j++) acc[i][j]=0.f;

    for (int k0 = 0; k0 < K; k0 += BK) {
        float4 a4 = *(const float4*)&A[(size_t)(bm + lrow)*K + k0 + lcol];
        float4 b4 = *(const float4*)&B[(size_t)(bn + lrow)*K + k0 + lcol];
        *(float4*)&As[lrow][lcol] = a4;
        *(float4*)&Bs[lrow][lcol] = b4;
        __syncthreads();
        #pragma unroll
        for (int kk = 0; kk < BK; kk++) {
            float a[4], bb[4];
            #pragma unroll
            for (int i=0;i<4;i++) a[i]  = As[ty*4+i][kk];
            #pragma unroll
            for (int j=0;j<4;j++) bb[j] = Bs[tx*4+j][kk];
            #pragma unroll
            for (int i=0;i<4;i++)
                #pragma unroll
                for (int j=0;j<4;j++) acc[i][j] += a[i]*bb[j];
        }
        __syncthreads();
    }

    if (EPI == 2) {
        __shared__ float red[16][65];
        #pragma unroll
        for (int i=0;i<4;i++) {
            float sv = 0.f;
            #pragma unroll
            for (int j=0;j<4;j++) sv += acc[i][j] + bias[bn + tx*4 + j];
            red[tx][ty*4+i] = sv;
        }
        __syncthreads();
        if (tid < 64) {
            float sv = 0.f;
            #pragma unroll
            for (int u=0;u<16;u++) sv += red[u][tid];
            atomicAdd(&rowsum[bm + tid], sv);
        }
    } else {
        #pragma unroll
        for (int i=0;i<4;i++) {
            int r = bm + ty*4 + i;
            #pragma unroll
            for (int j=0;j<4;j++) {
                int c = bn + tx*4 + j;
                float v = acc[i][j] + bias[c];
                if (EPI == 1) v = 0.5f*v*(1.f + erff(v*0.7071067811865476f));
                C[(size_t)r*N + c] = v;
            }
        }
    }
}

// ---------------- Attention: windowed causal, exact softmax ----------------
__global__ __launch_bounds__(256) void attn_kernel() {
    __shared__ float Qs[64][33];
    __shared__ float Ks[128][33];
    __shared__ float Vs[128][33];
    __shared__ float Ps[8][128];
    int qtile = blockIdx.x;            // 0..7
    int h     = blockIdx.y;            // 0..3
    int s     = blockIdx.z;            // 0..127
    int q0 = qtile * 64;
    int tid = threadIdx.x;

    for (int i = tid; i < 64*32; i += 256) {
        int r = i >> 5, c = i & 31;
        Qs[r][c] = g_QK[(size_t)(s*Tc + q0 + r)*(2*Dc) + h*HDc + c];
    }
    for (int i = tid; i < 128*32; i += 256) {
        int r = i >> 5, c = i & 31;
        int kt = q0 - 64 + r;
        float kv = 0.f, vv = 0.f;
        if (kt >= 0) {
            kv = g_QK[(size_t)(s*Tc + kt)*(2*Dc) + Dc + h*HDc + c];
            vv = g_V [(size_t)(s*Tc + kt)*Dc + h*HDc + c];
        }
        Ks[r][c] = kv; Vs[r][c] = vv;
    }
    __syncthreads();

    int warp = tid >> 5, lane = tid & 31;
    const float scale = 0.17677669529663687f; // 1/sqrt(32)
    for (int qi = 0; qi < 8; qi++) {
        int q = warp*8 + qi;
        int qt_g = q0 + q;
        float sc[4];
        #pragma unroll
        for (int j=0;j<4;j++) {
            int k = j*32 + lane;
            float dot = 0.f;
            #pragma unroll
            for (int dd=0; dd<32; dd++) dot += Qs[q][dd]*Ks[k][dd];
            int kt = q0 - 64 + k;
            bool ok = (kt >= 0) && (kt <= qt_g) && (qt_g - kt <= WINc);
            sc[j] = ok ? dot*scale : -INFINITY;
        }
        float mx = fmaxf(fmaxf(sc[0],sc[1]), fmaxf(sc[2],sc[3]));
        #pragma unroll
        for (int o=16;o;o>>=1) mx = fmaxf(mx, __shfl_xor_sync(0xffffffffu, mx, o));
        float sum = 0.f;
        #pragma unroll
        for (int j=0;j<4;j++) { sc[j] = __expf(sc[j]-mx) * (sc[j] > -INFINITY ? 1.f : 0.f); sum += sc[j]; }
        #pragma unroll
        for (int o=16;o;o>>=1) sum += __shfl_xor_sync(0xffffffffu, sum, o);
        float inv = 1.f/sum;
        #pragma unroll
        for (int j=0;j<4;j++) Ps[warp][j*32+lane] = sc[j]*inv;
        __syncwarp();
        float ov = 0.f;
        for (int k=0;k<128;k++) ov += Ps[warp][k]*Vs[k][lane];
        g_O[(size_t)(s*Tc + qt_g)*Dc + h*HDc + lane] = ov;
        __syncwarp();
    }
}

// ---------------- K4b: h2 = hcf + y ; LN2 -> h3 ; rowsum(h2) seed ----------------
// y lives in g_h1 (reused), h3 is written into g_qk (reused).
__global__ void k4b_add_ln(const float* __restrict__ gamma2,
                           const float* __restrict__ beta2) {
    __shared__ float sbuf[4];
    int row = blockIdx.x;
    int d = threadIdx.x;
    int idx = row*Dc + d;
    float h2v = g_hcf[idx] + g_h1[idx];           // hcf + y
    float mean = block_reduce_sum128(h2v, sbuf) * (1.f/Dc);
    float dv = h2v - mean;
    float var = block_reduce_sum128(dv*dv, sbuf) * (1.f/Dc);
    float h3v = dv * rsqrtf(var + 1e-5f) * gamma2[d] + beta2[d];
    g_qk[idx] = h3v;                              // h3
    if (d == 0) g_ysum[row] = mean * (float)Dc;   // sum(h2 row); W2 gemm adds ffn rowsums
}

// ---------------- K7: final combine ----------------
__global__ void k7_final(const float* __restrict__ x,
                         const float* __restrict__ W_in,
                         const float* __restrict__ b_in,
                         const float* __restrict__ W_out,
                         const float* __restrict__ b_out,
                         float* __restrict__ out) {
    __shared__ float xs[Fc];
    __shared__ float xw[Dc];
    int bt = blockIdx.x;               // b*T + t
    int tid = threadIdx.x;             // 128
    if (tid < Fc) xs[tid] = x[bt*Fc + tid];
    __syncthreads();
    float acc = b_in[tid];
    #pragma unroll
    for (int f=0; f<Fc; f++) acc += xs[f]*W_in[tid*Fc + f];
    xw[tid] = acc;
    __syncthreads();
    if (tid < Fc) {
        float yp = b_out[tid];
        for (int dd=0; dd<Dc; dd++) yp += xw[dd]*W_out[tid*Dc + dd];
        int b = bt >> 9, t = bt & (Tc-1);
        int srow = (b*Fc + tid)*Tc + t;
        float ymean = g_ysum[srow] * (1.f/(float)Dc);
        out[bt*Fc + tid] = xs[tid] + ymean + yp;
    }
}

// ---------------- launcher ----------------
extern "C" void kernel_launch(void* const* d_in, const int* in_sizes, int n_in,
                              void* d_out, int out_size) {
    const float* x      = (const float*)d_in[0];
    const float* W_in   = (const float*)d_in[1];
    const float* b_in   = (const float*)d_in[2];
    const float* gamma1 = (const float*)d_in[3];
    const float* beta1  = (const float*)d_in[4];
    const float* gamma2 = (const float*)d_in[5];
    const float* beta2  = (const float*)d_in[6];
    const float* W_qkv  = (const float*)d_in[7];
    const float* b_qkv  = (const float*)d_in[8];
    const float* W_o    = (const float*)d_in[9];
    const float* b_o    = (const float*)d_in[10];
    const float* W1     = (const float*)d_in[11];
    const float* b1     = (const float*)d_in[12];
    const float* W2     = (const float*)d_in[13];
    const float* b2     = (const float*)d_in[14];
    const float* W_out  = (const float*)d_in[15];
    const float* b_out  = (const float*)d_in[16];
    float* out = (float*)d_out;

    float *p_h1, *p_qk, *p_QK, *p_V, *p_O, *p_g, *p_ysum;
    cudaGetSymbolAddress((void**)&p_h1,   g_h1);
    cudaGetSymbolAddress((void**)&p_qk,   g_qk);
    cudaGetSymbolAddress((void**)&p_QK,   g_QK);
    cudaGetSymbolAddress((void**)&p_V,    g_V);
    cudaGetSymbolAddress((void**)&p_O,    g_O);
    cudaGetSymbolAddress((void**)&p_g,    g_g);
    cudaGetSymbolAddress((void**)&p_ysum, g_ysum);

    // 1) hcf + LN1 + RoPE
    k1_hcf_ln_rope<<<ROWS, 128>>>(x, W_in, b_in, gamma1, beta1);
    // 2) Q,K = qk @ [Wq;Wk]^T + b
    gemm_nt<0><<<dim3(256/BN, ROWS/BM), 256>>>(p_qk, W_qkv, b_qkv, p_QK, ROWS, 2*Dc, Dc, nullptr);
    // 3) V = h1 @ Wv^T + b
    gemm_nt<0><<<dim3(Dc/BN, ROWS/BM), 256>>>(p_h1, W_qkv + 2*Dc*Dc, b_qkv + 2*Dc, p_V, ROWS, Dc, Dc, nullptr);
    // 4) attention
    attn_kernel<<<dim3(Tc/64, NHc, Sc), 256>>>();
    // 5) y = O @ W_o^T + b_o   (y -> g_h1, h1 is dead now)
    gemm_nt<0><<<dim3(Dc/BN, ROWS/BM), 256>>>(p_O, W_o, b_o, p_h1, ROWS, Dc, Dc, nullptr);
    // 6) h2, LN2 -> h3 (into g_qk), seed rowsums
    k4b_add_ln<<<ROWS, 128>>>(gamma2, beta2);
    // 7) g = gelu(h3 @ W1^T + b1)
    gemm_nt<1><<<dim3(HIDc/BN, ROWS/BM), 256>>>(p_qk, W1, b1, p_g, ROWS, HIDc, Dc, nullptr);
    // 8) rowsum(g @ W2^T + b2) accumulated into ysum
    gemm_nt<2><<<dim3(Dc/BN, ROWS/BM), 256>>>(p_g, W2, b2, nullptr, ROWS, Dc, HIDc, p_ysum);
    // 9) final combine
    k7_final<<<Bc*Tc, 128>>>(x, W_in, b_in, W_out, b_out, out);
}

// round 7
// speedup vs baseline: 3.1875x; 3.1875x over previous
#include <cuda_runtime.h>
#include <cuda_bf16.h>
#include <math.h>
#include <stdint.h>

// Problem constants
#define Bc   4
#define Tc   512
#define Fc   32
#define Dc   128
#define NHc  4
#define HDc  32
#define WINc 64
#define HIDc 512
#define Sc   (Bc*Fc)          // 128 sequences
#define ROWS (Sc*Tc)          // 65536 rows

// ---------------- scratch (device globals; no allocation) ----------------
__device__ float g_hcf[ROWS*Dc];        // fp32 residual
__device__ float g_QK [ROWS*2*Dc];      // Q | K fp32 (attn input)
__device__ float g_V  [ROWS*Dc];        // fp32 (attn input)
__device__ float g_y  [ROWS*Dc];        // fp32 (residual add)
__device__ float g_ysum[ROWS];

__device__ __nv_bfloat16 g_h1bf[ROWS*Dc];
__device__ __nv_bfloat16 g_qkbf[ROWS*Dc];
__device__ __nv_bfloat16 g_Obf [ROWS*Dc];
__device__ __nv_bfloat16 g_h3bf[ROWS*Dc];
__device__ __nv_bfloat16 g_gbf [ROWS*HIDc];

__device__ __nv_bfloat16 g_Wqkv_bf[3*Dc*Dc];
__device__ __nv_bfloat16 g_Wo_bf  [Dc*Dc];
__device__ __nv_bfloat16 g_W1_bf  [HIDc*Dc];
__device__ __nv_bfloat16 g_W2_bf  [Dc*HIDc];

// ---------------- weight conversion ----------------
__global__ void conv_weights(const float* __restrict__ Wqkv,
                             const float* __restrict__ Wo,
                             const float* __restrict__ W1,
                             const float* __restrict__ W2) {
    int i = blockIdx.x*blockDim.x + threadIdx.x;
    if (i < 3*Dc*Dc)  g_Wqkv_bf[i] = __float2bfloat16(Wqkv[i]);
    if (i < Dc*Dc)    g_Wo_bf[i]   = __float2bfloat16(Wo[i]);
    if (i < HIDc*Dc)  g_W1_bf[i]   = __float2bfloat16(W1[i]);
    if (i < Dc*HIDc)  g_W2_bf[i]   = __float2bfloat16(W2[i]);
}

// ---------------- block reduce (128 threads, 4 warps) ----------------
__device__ __forceinline__ float block_reduce_sum128(float v, float* sbuf) {
    int lane = threadIdx.x & 31, w = threadIdx.x >> 5;
    #pragma unroll
    for (int o = 16; o; o >>= 1) v += __shfl_xor_sync(0xffffffffu, v, o);
    if (lane == 0) sbuf[w] = v;
    __syncthreads();
    float r = 0.f;
    if (w == 0) {
        r = (lane < 4) ? sbuf[lane] : 0.f;
        #pragma unroll
        for (int o = 2; o; o >>= 1) r += __shfl_xor_sync(0xffffffffu, r, o);
        if (lane == 0) sbuf[0] = r;
    }
    __syncthreads();
    r = sbuf[0];
    __syncthreads();
    return r;
}

// ---------------- K1: hcf (outer product) + LN1 + RoPE ----------------
__global__ void k1_hcf_ln_rope(const float* __restrict__ x,
                               const float* __restrict__ W_in,
                               const float* __restrict__ b_in,
                               const float* __restrict__ gamma1,
                               const float* __restrict__ beta1) {
    __shared__ float sbuf[4];
    int row = blockIdx.x;              // s*T + t
    int d   = threadIdx.x;             // 0..127
    int s = row >> 9, t = row & (Tc-1);
    int b = s >> 5, f = s & (Fc-1);

    float hv = x[(b*Tc + t)*Fc + f] * W_in[d*Fc + f] + b_in[d];

    float mean = block_reduce_sum128(hv, sbuf) * (1.f/Dc);
    float dv = hv - mean;
    float var = block_reduce_sum128(dv*dv, sbuf) * (1.f/Dc);
    float h1v = dv * rsqrtf(var + 1e-5f) * gamma1[d] + beta1[d];

    g_hcf [row*Dc + d] = hv;
    g_h1bf[row*Dc + d] = __float2bfloat16(h1v);

    // RoPE
    float part = __shfl_xor_sync(0xffffffffu, h1v, 1);
    int hd = d & (HDc-1);
    int i2 = hd >> 1;
    float inv = expf(-(float)(2*i2) * (9.210340371976184f / (float)HDc));
    float fr  = (float)t * inv;
    float sn = sinf(fr), cs = cosf(fr);
    float qv = ((d & 1) == 0) ? (h1v*cs - part*sn) : (part*sn + h1v*cs);
    g_qkbf[row*Dc + d] = __float2bfloat16(qv);
}

// ---------------- bf16 tensor-core GEMM: C[M,N] = A[M,K] @ B[N,K]^T + bias ----
// EPI 0: Cf = acc+bias (fp32) ; EPI 1: Cbf = gelu(acc+bias) (bf16)
// EPI 2: rowsum(acc+bias) -> atomicAdd rowsum[], no C
#define PKS 40   // padded smem K-stride (bf16 elems): 80B rows, conflict-free ldmatrix

__device__ __forceinline__ uint32_t smem_u32(const void* p) {
    return (uint32_t)__cvta_generic_to_shared(p);
}

template<int EPI>
__global__ __launch_bounds__(256) void gemm_bf16(
    const __nv_bfloat16* __restrict__ A,
    const __nv_bfloat16* __restrict__ B,
    const float* __restrict__ bias,
    float* __restrict__ Cf,
    __nv_bfloat16* __restrict__ Cbf,
    int M, int N, int K,
    float* __restrict__ rowsum)
{
    __shared__ __nv_bfloat16 As[128*PKS];
    __shared__ __nv_bfloat16 Bs[64*PKS];
    const int bm = blockIdx.y * 128;
    const int bn = blockIdx.x * 64;
    const int tid  = threadIdx.x;
    const int warp = tid >> 5, lane = tid & 31;
    const int wm = warp >> 1;      // 0..3 : m offset wm*32
    const int wn = warp & 1;       // 0..1 : n offset wn*32

    float acc[2][4][4];
    #pragma unroll
    for (int mi=0;mi<2;mi++)
        #pragma unroll
        for (int ni=0;ni<4;ni++)
            #pragma unroll
            for (int j=0;j<4;j++) acc[mi][ni][j] = 0.f;

    const int lrow = tid >> 2;          // 0..63
    const int lcol = (tid & 3) * 8;     // 0,8,16,24

    for (int k0 = 0; k0 < K; k0 += 32) {
        uint4 a0 = *(const uint4*)&A[(size_t)(bm + lrow)*K + k0 + lcol];
        uint4 a1 = *(const uint4*)&A[(size_t)(bm + 64 + lrow)*K + k0 + lcol];
        uint4 b0 = *(const uint4*)&B[(size_t)(bn + lrow)*K + k0 + lcol];
        __syncthreads();
        *(uint4*)&As[lrow*PKS + lcol]      = a0;
        *(uint4*)&As[(64+lrow)*PKS + lcol] = a1;
        *(uint4*)&Bs[lrow*PKS + lcol]      = b0;
        __syncthreads();

        #pragma unroll
        for (int ks = 0; ks < 2; ks++) {
            uint32_t af[2][4], bfr[4][2];
            #pragma unroll
            for (int mi=0;mi<2;mi++) {
                int row = wm*32 + mi*16 + (lane & 15);
                int col = ks*16 + (lane >> 4)*8;
                uint32_t addr = smem_u32(&As[row*PKS + col]);
                asm volatile("ldmatrix.sync.aligned.m8n8.x4.shared.b16 {%0,%1,%2,%3}, [%4];"
                    : "=r"(af[mi][0]),"=r"(af[mi][1]),"=r"(af[mi][2]),"=r"(af[mi][3])
                    : "r"(addr));
            }
            #pragma unroll
            for (int ni=0;ni<4;ni++) {
                int row = wn*32 + ni*8 + (lane & 7);
                int col = ks*16 + ((lane >> 3)&1)*8;
                uint32_t addr = smem_u32(&Bs[row*PKS + col]);
                asm volatile("ldmatrix.sync.aligned.m8n8.x2.shared.b16 {%0,%1}, [%2];"
                    : "=r"(bfr[ni][0]),"=r"(bfr[ni][1]) : "r"(addr));
            }
            #pragma unroll
            for (int mi=0;mi<2;mi++)
                #pragma unroll
                for (int ni=0;ni<4;ni++)
                    asm volatile("mma.sync.aligned.m16n8k16.row.col.f32.bf16.bf16.f32 "
                        "{%0,%1,%2,%3}, {%4,%5,%6,%7}, {%8,%9}, {%0,%1,%2,%3};"
                        : "+f"(acc[mi][ni][0]),"+f"(acc[mi][ni][1]),
                          "+f"(acc[mi][ni][2]),"+f"(acc[mi][ni][3])
                        : "r"(af[mi][0]),"r"(af[mi][1]),"r"(af[mi][2]),"r"(af[mi][3]),
                          "r"(bfr[ni][0]),"r"(bfr[ni][1]));
        }
    }

    // ---------------- epilogue ----------------
    if (EPI == 2) {
        #pragma unroll
        for (int mi=0;mi<2;mi++) {
            float s0 = 0.f, s1 = 0.f;
            #pragma unroll
            for (int ni=0;ni<4;ni++) {
                int c = bn + wn*32 + ni*8 + (lane&3)*2;
                float b0v = bias[c], b1v = bias[c+1];
                s0 += acc[mi][ni][0] + b0v + acc[mi][ni][1] + b1v;
                s1 += acc[mi][ni][2] + b0v + acc[mi][ni][3] + b1v;
            }
            s0 += __shfl_xor_sync(0xffffffffu, s0, 1);
            s0 += __shfl_xor_sync(0xffffffffu, s0, 2);
            s1 += __shfl_xor_sync(0xffffffffu, s1, 1);
            s1 += __shfl_xor_sync(0xffffffffu, s1, 2);
            if ((lane&3) == 0) {
                int r = bm + wm*32 + mi*16 + (lane>>2);
                atomicAdd(&rowsum[r],     s0);
                atomicAdd(&rowsum[r+8],   s1);
            }
        }
    } else {
        #pragma unroll
        for (int mi=0;mi<2;mi++) {
            int r0 = bm + wm*32 + mi*16 + (lane>>2);
            #pragma unroll
            for (int ni=0;ni<4;ni++) {
                int c = bn + wn*32 + ni*8 + (lane&3)*2;
                float v0 = acc[mi][ni][0] + bias[c];
                float v1 = acc[mi][ni][1] + bias[c+1];
                float v2 = acc[mi][ni][2] + bias[c];
                float v3 = acc[mi][ni][3] + bias[c+1];
                if (EPI == 1) {
                    v0 = 0.5f*v0*(1.f + erff(v0*0.7071067811865476f));
                    v1 = 0.5f*v1*(1.f + erff(v1*0.7071067811865476f));
                    v2 = 0.5f*v2*(1.f + erff(v2*0.7071067811865476f));
                    v3 = 0.5f*v3*(1.f + erff(v3*0.7071067811865476f));
                    __nv_bfloat162 p0 = __floats2bfloat162_rn(v0, v1);
                    __nv_bfloat162 p1 = __floats2bfloat162_rn(v2, v3);
                    *(__nv_bfloat162*)&Cbf[(size_t)r0*N + c]     = p0;
                    *(__nv_bfloat162*)&Cbf[(size_t)(r0+8)*N + c] = p1;
                } else {
                    *(float2*)&Cf[(size_t)r0*N + c]     = make_float2(v0, v1);
                    *(float2*)&Cf[(size_t)(r0+8)*N + c] = make_float2(v2, v3);
                }
            }
        }
    }
}

// ---------------- Attention: windowed causal, exact softmax ----------------
__global__ __launch_bounds__(256) void attn_kernel() {
    __shared__ float Qs[64][33];
    __shared__ float Ks[128][33];
    __shared__ float Vs[128][33];
    __shared__ float Ps[8][128];
    int qtile = blockIdx.x;            // 0..7
    int h     = blockIdx.y;            // 0..3
    int s     = blockIdx.z;            // 0..127
    int q0 = qtile * 64;
    int tid = threadIdx.x;

    for (int i = tid; i < 64*32; i += 256) {
        int r = i >> 5, c = i & 31;
        Qs[r][c] = g_QK[(size_t)(s*Tc + q0 + r)*(2*Dc) + h*HDc + c];
    }
    for (int i = tid; i < 128*32; i += 256) {
        int r = i >> 5, c = i & 31;
        int kt = q0 - 64 + r;
        float kv = 0.f, vv = 0.f;
        if (kt >= 0) {
            kv = g_QK[(size_t)(s*Tc + kt)*(2*Dc) + Dc + h*HDc + c];
            vv = g_V [(size_t)(s*Tc + kt)*Dc + h*HDc + c];
        }
        Ks[r][c] = kv; Vs[r][c] = vv;
    }
    __syncthreads();

    int warp = tid >> 5, lane = tid & 31;
    const float scale = 0.17677669529663687f; // 1/sqrt(32)
    for (int qi = 0; qi < 8; qi++) {
        int q = warp*8 + qi;
        int qt_g = q0 + q;
        float sc[4];
        #pragma unroll
        for (int j=0;j<4;j++) {
            int k = j*32 + lane;
            float dot = 0.f;
            #pragma unroll
            for (int dd=0; dd<32; dd++) dot += Qs[q][dd]*Ks[k][dd];
            int kt = q0 - 64 + k;
            bool ok = (kt >= 0) && (kt <= qt_g) && (qt_g - kt <= WINc);
            sc[j] = ok ? dot*scale : -INFINITY;
        }
        float mx = fmaxf(fmaxf(sc[0],sc[1]), fmaxf(sc[2],sc[3]));
        #pragma unroll
        for (int o=16;o;o>>=1) mx = fmaxf(mx, __shfl_xor_sync(0xffffffffu, mx, o));
        float sum = 0.f;
        #pragma unroll
        for (int j=0;j<4;j++) { sc[j] = __expf(sc[j]-mx) * (sc[j] > -INFINITY ? 1.f : 0.f); sum += sc[j]; }
        #pragma unroll
        for (int o=16;o;o>>=1) sum += __shfl_xor_sync(0xffffffffu, sum, o);
        float inv = 1.f/sum;
        #pragma unroll
        for (int j=0;j<4;j++) Ps[warp][j*32+lane] = sc[j]*inv;
        __syncwarp();
        float ov = 0.f;
        for (int k=0;k<128;k++) ov += Ps[warp][k]*Vs[k][lane];
        g_Obf[(size_t)(s*Tc + qt_g)*Dc + h*HDc + lane] = __float2bfloat16(ov);
        __syncwarp();
    }
}

// ---------------- K4b: h2 = hcf + y ; LN2 -> h3(bf16) ; rowsum(h2) seed ------
__global__ void k4b_add_ln(const float* __restrict__ gamma2,
                           const float* __restrict__ beta2) {
    __shared__ float sbuf[4];
    int row = blockIdx.x;
    int d = threadIdx.x;
    int idx = row*Dc + d;
    float h2v = g_hcf[idx] + g_y[idx];
    float mean = block_reduce_sum128(h2v, sbuf) * (1.f/Dc);
    float dv = h2v - mean;
    float var = block_reduce_sum128(dv*dv, sbuf) * (1.f/Dc);
    float h3v = dv * rsqrtf(var + 1e-5f) * gamma2[d] + beta2[d];
    g_h3bf[idx] = __float2bfloat16(h3v);
    if (d == 0) g_ysum[row] = mean * (float)Dc;   // sum(h2 row)
}

// ---------------- K7: final combine ----------------
__global__ void k7_final(const float* __restrict__ x,
                         const float* __restrict__ W_in,
                         const float* __restrict__ b_in,
                         const float* __restrict__ W_out,
                         const float* __restrict__ b_out,
                         float* __restrict__ out) {
    __shared__ float xs[Fc];
    __shared__ float xw[Dc];
    int bt = blockIdx.x;               // b*T + t
    int tid = threadIdx.x;             // 128
    if (tid < Fc) xs[tid] = x[bt*Fc + tid];
    __syncthreads();
    float acc = b_in[tid];
    #pragma unroll
    for (int f=0; f<Fc; f++) acc += xs[f]*W_in[tid*Fc + f];
    xw[tid] = acc;
    __syncthreads();
    if (tid < Fc) {
        float yp = b_out[tid];
        for (int dd=0; dd<Dc; dd++) yp += xw[dd]*W_out[tid*Dc + dd];
        int b = bt >> 9, t = bt & (Tc-1);
        int srow = (b*Fc + tid)*Tc + t;
        float ymean = g_ysum[srow] * (1.f/(float)Dc);
        out[bt*Fc + tid] = xs[tid] + ymean + yp;
    }
}

// ---------------- launcher ----------------
extern "C" void kernel_launch(void* const* d_in, const int* in_sizes, int n_in,
                              void* d_out, int out_size) {
    const float* x      = (const float*)d_in[0];
    const float* W_in   = (const float*)d_in[1];
    const float* b_in   = (const float*)d_in[2];
    const float* gamma1 = (const float*)d_in[3];
    const float* beta1  = (const float*)d_in[4];
    const float* gamma2 = (const float*)d_in[5];
    const float* beta2  = (const float*)d_in[6];
    const float* W_qkv  = (const float*)d_in[7];
    const float* b_qkv  = (const float*)d_in[8];
    const float* W_o    = (const float*)d_in[9];
    const float* b_o    = (const float*)d_in[10];
    const float* W1     = (const float*)d_in[11];
    const float* b1     = (const float*)d_in[12];
    const float* W2     = (const float*)d_in[13];
    const float* b2     = (const float*)d_in[14];
    const float* W_out  = (const float*)d_in[15];
    const float* b_out  = (const float*)d_in[16];
    float* out = (float*)d_out;

    float *p_QK, *p_V, *p_y, *p_ysum;
    __nv_bfloat16 *p_h1bf, *p_qkbf, *p_Obf, *p_h3bf, *p_gbf;
    __nv_bfloat16 *p_Wqkv, *p_Wo, *p_W1, *p_W2;
    cudaGetSymbolAddress((void**)&p_QK,   g_QK);
    cudaGetSymbolAddress((void**)&p_V,    g_V);
    cudaGetSymbolAddress((void**)&p_y,    g_y);
    cudaGetSymbolAddress((void**)&p_ysum, g_ysum);
    cudaGetSymbolAddress((void**)&p_h1bf, g_h1bf);
    cudaGetSymbolAddress((void**)&p_qkbf, g_qkbf);
    cudaGetSymbolAddress((void**)&p_Obf,  g_Obf);
    cudaGetSymbolAddress((void**)&p_h3bf, g_h3bf);
    cudaGetSymbolAddress((void**)&p_gbf,  g_gbf);
    cudaGetSymbolAddress((void**)&p_Wqkv, g_Wqkv_bf);
    cudaGetSymbolAddress((void**)&p_Wo,   g_Wo_bf);
    cudaGetSymbolAddress((void**)&p_W1,   g_W1_bf);
    cudaGetSymbolAddress((void**)&p_W2,   g_W2_bf);

    // 0) weights -> bf16
    conv_weights<<<(HIDc*Dc + 255)/256, 256>>>(W_qkv, W_o, W1, W2);
    // 1) hcf + LN1 + RoPE
    k1_hcf_ln_rope<<<ROWS, 128>>>(x, W_in, b_in, gamma1, beta1);
    // 2) Q,K = qk @ [Wq;Wk]^T + b        (M=ROWS, N=256, K=128)
    gemm_bf16<0><<<dim3(4, ROWS/128), 256>>>(p_qkbf, p_Wqkv, b_qkv, p_QK, nullptr, ROWS, 256, 128, nullptr);
    // 3) V = h1 @ Wv^T + b               (N=128)
    gemm_bf16<0><<<dim3(2, ROWS/128), 256>>>(p_h1bf, p_Wqkv + 2*Dc*Dc, b_qkv + 2*Dc, p_V, nullptr, ROWS, 128, 128, nullptr);
    // 4) attention (writes O as bf16)
    attn_kernel<<<dim3(Tc/64, NHc, Sc), 256>>>();
    // 5) y = O @ W_o^T + b_o             (N=128)
    gemm_bf16<0><<<dim3(2, ROWS/128), 256>>>(p_Obf, p_Wo, b_o, p_y, nullptr, ROWS, 128, 128, nullptr);
    // 6) h2, LN2 -> h3 (bf16), seed rowsums
    k4b_add_ln<<<ROWS, 128>>>(gamma2, beta2);
    // 7) g = gelu(h3 @ W1^T + b1) (bf16) (N=512)
    gemm_bf16<1><<<dim3(8, ROWS/128), 256>>>(p_h3bf, p_W1, b1, nullptr, p_gbf, ROWS, 512, 128, nullptr);
    // 8) rowsum(g @ W2^T + b2) -> ysum   (N=128, K=512)
    gemm_bf16<2><<<dim3(2, ROWS/128), 256>>>(p_gbf, p_W2, b2, nullptr, nullptr, ROWS, 128, 512, p_ysum);
    // 9) final combine
    k7_final<<<Bc*Tc, 128>>>(x, W_in, b_in, W_out, b_out, out);
}

// round 8
// speedup vs baseline: 5.3533x; 1.6795x over previous
#include <cuda_runtime.h>
#include <cuda_bf16.h>
#include <math.h>
#include <stdint.h>

// Problem constants
#define Bc   4
#define Tc   512
#define Fc   32
#define Dc   128
#define NHc  4
#define HDc  32
#define WINc 64
#define HIDc 512
#define Sc   (Bc*Fc)          // 128 sequences
#define ROWS (Sc*Tc)          // 65536 rows

// ---------------- scratch (device globals; no allocation) ----------------
__device__ float g_hcf[ROWS*Dc];        // fp32 residual
__device__ float g_y  [ROWS*Dc];        // fp32 (residual add)
__device__ float g_ysum[ROWS];

__device__ __nv_bfloat16 g_h1bf[ROWS*Dc];
__device__ __nv_bfloat16 g_qkbf[ROWS*Dc];      // LN1+rope (QK gemm input)
__device__ __nv_bfloat16 g_QKo [ROWS*2*Dc];    // Q|K bf16 (gemm output, attn input)
__device__ __nv_bfloat16 g_Vbf [ROWS*Dc];      // V bf16
__device__ __nv_bfloat16 g_Obf [ROWS*Dc];
__device__ __nv_bfloat16 g_h3bf[ROWS*Dc];
__device__ __nv_bfloat16 g_gbf [ROWS*HIDc];

__device__ __nv_bfloat16 g_Wqkv_bf[3*Dc*Dc];
__device__ __nv_bfloat16 g_Wo_bf  [Dc*Dc];
__device__ __nv_bfloat16 g_W1_bf  [HIDc*Dc];
__device__ __nv_bfloat16 g_W2_bf  [Dc*HIDc];

// ---------------- weight conversion ----------------
__global__ void conv_weights(const float* __restrict__ Wqkv,
                             const float* __restrict__ Wo,
                             const float* __restrict__ W1,
                             const float* __restrict__ W2) {
    int i = blockIdx.x*blockDim.x + threadIdx.x;
    if (i < 3*Dc*Dc)  g_Wqkv_bf[i] = __float2bfloat16(Wqkv[i]);
    if (i < Dc*Dc)    g_Wo_bf[i]   = __float2bfloat16(Wo[i]);
    if (i < HIDc*Dc)  g_W1_bf[i]   = __float2bfloat16(W1[i]);
    if (i < Dc*HIDc)  g_W2_bf[i]   = __float2bfloat16(W2[i]);
}

// ---------------- block reduce (128 threads, 4 warps) ----------------
__device__ __forceinline__ float block_reduce_sum128(float v, float* sbuf) {
    int lane = threadIdx.x & 31, w = threadIdx.x >> 5;
    #pragma unroll
    for (int o = 16; o; o >>= 1) v += __shfl_xor_sync(0xffffffffu, v, o);
    if (lane == 0) sbuf[w] = v;
    __syncthreads();
    float r = 0.f;
    if (w == 0) {
        r = (lane < 4) ? sbuf[lane] : 0.f;
        #pragma unroll
        for (int o = 2; o; o >>= 1) r += __shfl_xor_sync(0xffffffffu, r, o);
        if (lane == 0) sbuf[0] = r;
    }
    __syncthreads();
    r = sbuf[0];
    __syncthreads();
    return r;
}

// ---------------- K1: hcf (outer product) + LN1 + RoPE ----------------
__global__ void k1_hcf_ln_rope(const float* __restrict__ x,
                               const float* __restrict__ W_in,
                               const float* __restrict__ b_in,
                               const float* __restrict__ gamma1,
                               const float* __restrict__ beta1) {
    __shared__ float sbuf[4];
    int row = blockIdx.x;              // s*T + t
    int d   = threadIdx.x;             // 0..127
    int s = row >> 9, t = row & (Tc-1);
    int b = s >> 5, f = s & (Fc-1);

    float hv = x[(b*Tc + t)*Fc + f] * W_in[d*Fc + f] + b_in[d];

    float mean = block_reduce_sum128(hv, sbuf) * (1.f/Dc);
    float dv = hv - mean;
    float var = block_reduce_sum128(dv*dv, sbuf) * (1.f/Dc);
    float h1v = dv * rsqrtf(var + 1e-5f) * gamma1[d] + beta1[d];

    g_hcf [row*Dc + d] = hv;
    g_h1bf[row*Dc + d] = __float2bfloat16(h1v);

    // RoPE
    float part = __shfl_xor_sync(0xffffffffu, h1v, 1);
    int hd = d & (HDc-1);
    int i2 = hd >> 1;
    float inv = expf(-(float)(2*i2) * (9.210340371976184f / (float)HDc));
    float fr  = (float)t * inv;
    float sn = sinf(fr), cs = cosf(fr);
    float qv = ((d & 1) == 0) ? (h1v*cs - part*sn) : (part*sn + h1v*cs);
    g_qkbf[row*Dc + d] = __float2bfloat16(qv);
}

// ---------------- bf16 tensor-core GEMM: C[M,N] = A[M,K] @ B[N,K]^T + bias ----
// EPI 0: Cf = acc+bias (fp32) ; EPI 1: Cbf = gelu(acc+bias) (bf16)
// EPI 2: rowsum(acc+bias) -> atomicAdd ; EPI 3: Cbf = acc+bias (bf16)
#define PKS 40   // padded smem K-stride (bf16 elems)

__device__ __forceinline__ uint32_t smem_u32(const void* p) {
    return (uint32_t)__cvta_generic_to_shared(p);
}

template<int EPI>
__global__ __launch_bounds__(256) void gemm_bf16(
    const __nv_bfloat16* __restrict__ A,
    const __nv_bfloat16* __restrict__ B,
    const float* __restrict__ bias,
    float* __restrict__ Cf,
    __nv_bfloat16* __restrict__ Cbf,
    int M, int N, int K,
    float* __restrict__ rowsum)
{
    __shared__ __nv_bfloat16 As[128*PKS];
    __shared__ __nv_bfloat16 Bs[64*PKS];
    const int bm = blockIdx.y * 128;
    const int bn = blockIdx.x * 64;
    const int tid  = threadIdx.x;
    const int warp = tid >> 5, lane = tid & 31;
    const int wm = warp >> 1;
    const int wn = warp & 1;

    float acc[2][4][4];
    #pragma unroll
    for (int mi=0;mi<2;mi++)
        #pragma unroll
        for (int ni=0;ni<4;ni++)
            #pragma unroll
            for (int j=0;j<4;j++) acc[mi][ni][j] = 0.f;

    const int lrow = tid >> 2;
    const int lcol = (tid & 3) * 8;

    for (int k0 = 0; k0 < K; k0 += 32) {
        uint4 a0 = *(const uint4*)&A[(size_t)(bm + lrow)*K + k0 + lcol];
        uint4 a1 = *(const uint4*)&A[(size_t)(bm + 64 + lrow)*K + k0 + lcol];
        uint4 b0 = *(const uint4*)&B[(size_t)(bn + lrow)*K + k0 + lcol];
        __syncthreads();
        *(uint4*)&As[lrow*PKS + lcol]      = a0;
        *(uint4*)&As[(64+lrow)*PKS + lcol] = a1;
        *(uint4*)&Bs[lrow*PKS + lcol]      = b0;
        __syncthreads();

        #pragma unroll
        for (int ks = 0; ks < 2; ks++) {
            uint32_t af[2][4], bfr[4][2];
            #pragma unroll
            for (int mi=0;mi<2;mi++) {
                int row = wm*32 + mi*16 + (lane & 15);
                int col = ks*16 + (lane >> 4)*8;
                uint32_t addr = smem_u32(&As[row*PKS + col]);
                asm volatile("ldmatrix.sync.aligned.m8n8.x4.shared.b16 {%0,%1,%2,%3}, [%4];"
                    : "=r"(af[mi][0]),"=r"(af[mi][1]),"=r"(af[mi][2]),"=r"(af[mi][3])
                    : "r"(addr));
            }
            #pragma unroll
            for (int ni=0;ni<4;ni++) {
                int row = wn*32 + ni*8 + (lane & 7);
                int col = ks*16 + ((lane >> 3)&1)*8;
                uint32_t addr = smem_u32(&Bs[row*PKS + col]);
                asm volatile("ldmatrix.sync.aligned.m8n8.x2.shared.b16 {%0,%1}, [%2];"
                    : "=r"(bfr[ni][0]),"=r"(bfr[ni][1]) : "r"(addr));
            }
            #pragma unroll
            for (int mi=0;mi<2;mi++)
                #pragma unroll
                for (int ni=0;ni<4;ni++)
                    asm volatile("mma.sync.aligned.m16n8k16.row.col.f32.bf16.bf16.f32 "
                        "{%0,%1,%2,%3}, {%4,%5,%6,%7}, {%8,%9}, {%0,%1,%2,%3};"
                        : "+f"(acc[mi][ni][0]),"+f"(acc[mi][ni][1]),
                          "+f"(acc[mi][ni][2]),"+f"(acc[mi][ni][3])
                        : "r"(af[mi][0]),"r"(af[mi][1]),"r"(af[mi][2]),"r"(af[mi][3]),
                          "r"(bfr[ni][0]),"r"(bfr[ni][1]));
        }
    }

    // ---------------- epilogue ----------------
    if (EPI == 2) {
        #pragma unroll
        for (int mi=0;mi<2;mi++) {
            float s0 = 0.f, s1 = 0.f;
            #pragma unroll
            for (int ni=0;ni<4;ni++) {
                int c = bn + wn*32 + ni*8 + (lane&3)*2;
                float b0v = bias[c], b1v = bias[c+1];
                s0 += acc[mi][ni][0] + b0v + acc[mi][ni][1] + b1v;
                s1 += acc[mi][ni][2] + b0v + acc[mi][ni][3] + b1v;
            }
            s0 += __shfl_xor_sync(0xffffffffu, s0, 1);
            s0 += __shfl_xor_sync(0xffffffffu, s0, 2);
            s1 += __shfl_xor_sync(0xffffffffu, s1, 1);
            s1 += __shfl_xor_sync(0xffffffffu, s1, 2);
            if ((lane&3) == 0) {
                int r = bm + wm*32 + mi*16 + (lane>>2);
                atomicAdd(&rowsum[r],     s0);
                atomicAdd(&rowsum[r+8],   s1);
            }
        }
    } else {
        #pragma unroll
        for (int mi=0;mi<2;mi++) {
            int r0 = bm + wm*32 + mi*16 + (lane>>2);
            #pragma unroll
            for (int ni=0;ni<4;ni++) {
                int c = bn + wn*32 + ni*8 + (lane&3)*2;
                float v0 = acc[mi][ni][0] + bias[c];
                float v1 = acc[mi][ni][1] + bias[c+1];
                float v2 = acc[mi][ni][2] + bias[c];
                float v3 = acc[mi][ni][3] + bias[c+1];
                if (EPI == 1) {
                    v0 = 0.5f*v0*(1.f + erff(v0*0.7071067811865476f));
                    v1 = 0.5f*v1*(1.f + erff(v1*0.7071067811865476f));
                    v2 = 0.5f*v2*(1.f + erff(v2*0.7071067811865476f));
                    v3 = 0.5f*v3*(1.f + erff(v3*0.7071067811865476f));
                }
                if (EPI == 1 || EPI == 3) {
                    __nv_bfloat162 p0 = __floats2bfloat162_rn(v0, v1);
                    __nv_bfloat162 p1 = __floats2bfloat162_rn(v2, v3);
                    *(__nv_bfloat162*)&Cbf[(size_t)r0*N + c]     = p0;
                    *(__nv_bfloat162*)&Cbf[(size_t)(r0+8)*N + c] = p1;
                } else {
                    *(float2*)&Cf[(size_t)r0*N + c]     = make_float2(v0, v1);
                    *(float2*)&Cf[(size_t)(r0+8)*N + c] = make_float2(v2, v3);
                }
            }
        }
    }
}

// ---------------- Attention v2: tensor-core, windowed causal, exact softmax ---
// Block: (qtile 0..7, head 0..3, seq 0..127), 128 threads = 4 warps.
// Warp w handles queries q0 + w*16 .. +15 against the 128-key window.
#define QPAD 40    // 32+8 bf16 stride
#define VPAD 136   // 128+8 bf16 stride

__global__ __launch_bounds__(128) void attn_mma() {
    __shared__ __nv_bfloat16 Qs[64*QPAD];
    __shared__ __nv_bfloat16 Ks[128*QPAD];
    __shared__ __nv_bfloat16 Vt[32*VPAD];   // transposed: [hd][key]
    const int qtile = blockIdx.x, h = blockIdx.y, s = blockIdx.z;
    const int q0 = qtile*64;
    const int tid = threadIdx.x, warp = tid>>5, lane = tid&31;

    // load Q (64x32)
    for (int i = tid; i < 64*4; i += 128) {
        int r = i>>2, c4 = (i&3)*8;
        *(uint4*)&Qs[r*QPAD + c4] =
            *(const uint4*)&g_QKo[(size_t)(s*Tc + q0 + r)*(2*Dc) + h*HDc + c4];
    }
    // load K (128x32), keys q0-64 .. q0+63
    for (int i = tid; i < 128*4; i += 128) {
        int r = i>>2, c4 = (i&3)*8;
        int kt = q0 - 64 + r;
        uint4 val = make_uint4(0,0,0,0);
        if (kt >= 0)
            val = *(const uint4*)&g_QKo[(size_t)(s*Tc + kt)*(2*Dc) + Dc + h*HDc + c4];
        *(uint4*)&Ks[r*QPAD + c4] = val;
    }
    // load V transposed: Vt[hd][key]
    for (int i = tid; i < 128*32; i += 128) {
        int r = i>>5, c = i&31;
        int kt = q0 - 64 + r;
        __nv_bfloat16 v = __float2bfloat16(0.f);
        if (kt >= 0) v = g_Vbf[(size_t)(s*Tc + kt)*Dc + h*HDc + c];
        Vt[c*VPAD + r] = v;
    }
    __syncthreads();

    // Q A-fragments (2 k16 tiles over HD=32)
    uint32_t aq[2][4];
    #pragma unroll
    for (int kk=0; kk<2; kk++) {
        int row = warp*16 + (lane & 15);
        int col = kk*16 + (lane >> 4)*8;
        uint32_t addr = smem_u32(&Qs[row*QPAD + col]);
        asm volatile("ldmatrix.sync.aligned.m8n8.x4.shared.b16 {%0,%1,%2,%3}, [%4];"
            : "=r"(aq[kk][0]),"=r"(aq[kk][1]),"=r"(aq[kk][2]),"=r"(aq[kk][3])
            : "r"(addr));
    }

    // S = Q K^T : 16 n8-tiles over 128 keys
    float sc[16][4];
    #pragma unroll
    for (int ni=0; ni<16; ni++) { sc[ni][0]=sc[ni][1]=sc[ni][2]=sc[ni][3]=0.f; }
    #pragma unroll
    for (int ni=0; ni<16; ni++) {
        #pragma unroll
        for (int kk=0; kk<2; kk++) {
            uint32_t b0, b1;
            int row = ni*8 + (lane & 7);
            int col = kk*16 + ((lane >> 3)&1)*8;
            uint32_t addr = smem_u32(&Ks[row*QPAD + col]);
            asm volatile("ldmatrix.sync.aligned.m8n8.x2.shared.b16 {%0,%1}, [%2];"
                : "=r"(b0),"=r"(b1) : "r"(addr));
            asm volatile("mma.sync.aligned.m16n8k16.row.col.f32.bf16.bf16.f32 "
                "{%0,%1,%2,%3}, {%4,%5,%6,%7}, {%8,%9}, {%0,%1,%2,%3};"
                : "+f"(sc[ni][0]),"+f"(sc[ni][1]),"+f"(sc[ni][2]),"+f"(sc[ni][3])
                : "r"(aq[kk][0]),"r"(aq[kk][1]),"r"(aq[kk][2]),"r"(aq[kk][3]),
                  "r"(b0),"r"(b1));
        }
    }

    // mask + scale + softmax (rows qg0 = c0/c1, qg1 = c2/c3)
    const float scale = 0.17677669529663687f;
    const int g = lane >> 2, t4 = lane & 3;
    const int qg0 = q0 + warp*16 + g;
    const int qg1 = qg0 + 8;
    float mx0 = -INFINITY, mx1 = -INFINITY;
    #pragma unroll
    for (int ni=0; ni<16; ni++) {
        #pragma unroll
        for (int j=0; j<2; j++) {
            int col = ni*8 + 2*t4 + j;
            int kg = q0 - 64 + col;
            float v0 = sc[ni][j]   * scale;
            float v1 = sc[ni][2+j] * scale;
            bool ok0 = (kg >= 0) && (kg <= qg0) && (qg0 - kg <= WINc);
            bool ok1 = (kg >= 0) && (kg <= qg1) && (qg1 - kg <= WINc);
            sc[ni][j]   = ok0 ? v0 : -INFINITY;
            sc[ni][2+j] = ok1 ? v1 : -INFINITY;
            mx0 = fmaxf(mx0, sc[ni][j]);
            mx1 = fmaxf(mx1, sc[ni][2+j]);
        }
    }
    mx0 = fmaxf(mx0, __shfl_xor_sync(0xffffffffu, mx0, 1));
    mx0 = fmaxf(mx0, __shfl_xor_sync(0xffffffffu, mx0, 2));
    mx1 = fmaxf(mx1, __shfl_xor_sync(0xffffffffu, mx1, 1));
    mx1 = fmaxf(mx1, __shfl_xor_sync(0xffffffffu, mx1, 2));
    float sum0 = 0.f, sum1 = 0.f;
    #pragma unroll
    for (int ni=0; ni<16; ni++) {
        #pragma unroll
        for (int j=0; j<2; j++) {
            float e0 = (sc[ni][j]   > -INFINITY) ? __expf(sc[ni][j]   - mx0) : 0.f;
            float e1 = (sc[ni][2+j] > -INFINITY) ? __expf(sc[ni][2+j] - mx1) : 0.f;
            sc[ni][j] = e0; sc[ni][2+j] = e1;
            sum0 += e0; sum1 += e1;
        }
    }
    sum0 += __shfl_xor_sync(0xffffffffu, sum0, 1);
    sum0 += __shfl_xor_sync(0xffffffffu, sum0, 2);
    sum1 += __shfl_xor_sync(0xffffffffu, sum1, 1);
    sum1 += __shfl_xor_sync(0xffffffffu, sum1, 2);
    float inv0 = 1.f/sum0, inv1 = 1.f/sum1;

    // pack P into A-fragments: k16-tile kt8 = S tiles (2kt8, 2kt8+1)
    uint32_t pa[8][4];
    #pragma unroll
    for (int kt8=0; kt8<8; kt8++) {
        __nv_bfloat162 t0 = __floats2bfloat162_rn(sc[2*kt8][0]*inv0,   sc[2*kt8][1]*inv0);
        __nv_bfloat162 t1 = __floats2bfloat162_rn(sc[2*kt8][2]*inv1,   sc[2*kt8][3]*inv1);
        __nv_bfloat162 t2 = __floats2bfloat162_rn(sc[2*kt8+1][0]*inv0, sc[2*kt8+1][1]*inv0);
        __nv_bfloat162 t3 = __floats2bfloat162_rn(sc[2*kt8+1][2]*inv1, sc[2*kt8+1][3]*inv1);
        pa[kt8][0] = *(uint32_t*)&t0;
        pa[kt8][1] = *(uint32_t*)&t1;
        pa[kt8][2] = *(uint32_t*)&t2;
        pa[kt8][3] = *(uint32_t*)&t3;
    }

    // O = P V : 4 n8-tiles over HD=32, 8 k16-tiles over 128 keys
    float oacc[4][4];
    #pragma unroll
    for (int ni=0; ni<4; ni++) { oacc[ni][0]=oacc[ni][1]=oacc[ni][2]=oacc[ni][3]=0.f; }
    #pragma unroll
    for (int kt8=0; kt8<8; kt8++) {
        #pragma unroll
        for (int ni=0; ni<4; ni++) {
            uint32_t b0, b1;
            int row = ni*8 + (lane & 7);
            int col = kt8*16 + ((lane >> 3)&1)*8;
            uint32_t addr = smem_u32(&Vt[row*VPAD + col]);
            asm volatile("ldmatrix.sync.aligned.m8n8.x2.shared.b16 {%0,%1}, [%2];"
                : "=r"(b0),"=r"(b1) : "r"(addr));
            asm volatile("mma.sync.aligned.m16n8k16.row.col.f32.bf16.bf16.f32 "
                "{%0,%1,%2,%3}, {%4,%5,%6,%7}, {%8,%9}, {%0,%1,%2,%3};"
                : "+f"(oacc[ni][0]),"+f"(oacc[ni][1]),"+f"(oacc[ni][2]),"+f"(oacc[ni][3])
                : "r"(pa[kt8][0]),"r"(pa[kt8][1]),"r"(pa[kt8][2]),"r"(pa[kt8][3]),
                  "r"(b0),"r"(b1));
        }
    }

    // store O (bf16)
    #pragma unroll
    for (int ni=0; ni<4; ni++) {
        int col = ni*8 + 2*t4;
        __nv_bfloat162 p0 = __floats2bfloat162_rn(oacc[ni][0], oacc[ni][1]);
        __nv_bfloat162 p1 = __floats2bfloat162_rn(oacc[ni][2], oacc[ni][3]);
        *(__nv_bfloat162*)&g_Obf[(size_t)(s*Tc + qg0)*Dc + h*HDc + col] = p0;
        *(__nv_bfloat162*)&g_Obf[(size_t)(s*Tc + qg1)*Dc + h*HDc + col] = p1;
    }
}

// ---------------- K4b: h2 = hcf + y ; LN2 -> h3(bf16) ; rowsum(h2) seed ------
__global__ void k4b_add_ln(const float* __restrict__ gamma2,
                           const float* __restrict__ beta2) {
    __shared__ float sbuf[4];
    int row = blockIdx.x;
    int d = threadIdx.x;
    int idx = row*Dc + d;
    float h2v = g_hcf[idx] + g_y[idx];
    float mean = block_reduce_sum128(h2v, sbuf) * (1.f/Dc);
    float dv = h2v - mean;
    float var = block_reduce_sum128(dv*dv, sbuf) * (1.f/Dc);
    float h3v = dv * rsqrtf(var + 1e-5f) * gamma2[d] + beta2[d];
    g_h3bf[idx] = __float2bfloat16(h3v);
    if (d == 0) g_ysum[row] = mean * (float)Dc;   // sum(h2 row)
}

// ---------------- K7: final combine ----------------
__global__ void k7_final(const float* __restrict__ x,
                         const float* __restrict__ W_in,
                         const float* __restrict__ b_in,
                         const float* __restrict__ W_out,
                         const float* __restrict__ b_out,
                         float* __restrict__ out) {
    __shared__ float xs[Fc];
    __shared__ float xw[Dc];
    int bt = blockIdx.x;               // b*T + t
    int tid = threadIdx.x;             // 128
    if (tid < Fc) xs[tid] = x[bt*Fc + tid];
    __syncthreads();
    float acc = b_in[tid];
    #pragma unroll
    for (int f=0; f<Fc; f++) acc += xs[f]*W_in[tid*Fc + f];
    xw[tid] = acc;
    __syncthreads();
    if (tid < Fc) {
        float yp = b_out[tid];
        for (int dd=0; dd<Dc; dd++) yp += xw[dd]*W_out[tid*Dc + dd];
        int b = bt >> 9, t = bt & (Tc-1);
        int srow = (b*Fc + tid)*Tc + t;
        float ymean = g_ysum[srow] * (1.f/(float)Dc);
        out[bt*Fc + tid] = xs[tid] + ymean + yp;
    }
}

// ---------------- launcher ----------------
extern "C" void kernel_launch(void* const* d_in, const int* in_sizes, int n_in,
                              void* d_out, int out_size) {
    const float* x      = (const float*)d_in[0];
    const float* W_in   = (const float*)d_in[1];
    const float* b_in   = (const float*)d_in[2];
    const float* gamma1 = (const float*)d_in[3];
    const float* beta1  = (const float*)d_in[4];
    const float* gamma2 = (const float*)d_in[5];
    const float* beta2  = (const float*)d_in[6];
    const float* W_qkv  = (const float*)d_in[7];
    const float* b_qkv  = (const float*)d_in[8];
    const float* W_o    = (const float*)d_in[9];
    const float* b_o    = (const float*)d_in[10];
    const float* W1     = (const float*)d_in[11];
    const float* b1     = (const float*)d_in[12];
    const float* W2     = (const float*)d_in[13];
    const float* b2     = (const float*)d_in[14];
    const float* W_out  = (const float*)d_in[15];
    const float* b_out  = (const float*)d_in[16];
    float* out = (float*)d_out;

    float *p_y, *p_ysum;
    __nv_bfloat16 *p_h1bf, *p_qkbf, *p_QKo, *p_Vbf, *p_Obf, *p_h3bf, *p_gbf;
    __nv_bfloat16 *p_Wqkv, *p_Wo, *p_W1, *p_W2;
    cudaGetSymbolAddress((void**)&p_y,    g_y);
    cudaGetSymbolAddress((void**)&p_ysum, g_ysum);
    cudaGetSymbolAddress((void**)&p_h1bf, g_h1bf);
    cudaGetSymbolAddress((void**)&p_qkbf, g_qkbf);
    cudaGetSymbolAddress((void**)&p_QKo,  g_QKo);
    cudaGetSymbolAddress((void**)&p_Vbf,  g_Vbf);
    cudaGetSymbolAddress((void**)&p_Obf,  g_Obf);
    cudaGetSymbolAddress((void**)&p_h3bf, g_h3bf);
    cudaGetSymbolAddress((void**)&p_gbf,  g_gbf);
    cudaGetSymbolAddress((void**)&p_Wqkv, g_Wqkv_bf);
    cudaGetSymbolAddress((void**)&p_Wo,   g_Wo_bf);
    cudaGetSymbolAddress((void**)&p_W1,   g_W1_bf);
    cudaGetSymbolAddress((void**)&p_W2,   g_W2_bf);

    // 0) weights -> bf16
    conv_weights<<<(HIDc*Dc + 255)/256, 256>>>(W_qkv, W_o, W1, W2);
    // 1) hcf + LN1 + RoPE
    k1_hcf_ln_rope<<<ROWS, 128>>>(x, W_in, b_in, gamma1, beta1);
    // 2) Q,K = qk @ [Wq;Wk]^T + b  -> bf16   (N=256)
    gemm_bf16<3><<<dim3(4, ROWS/128), 256>>>(p_qkbf, p_Wqkv, b_qkv, nullptr, p_QKo, ROWS, 256, 128, nullptr);
    // 3) V = h1 @ Wv^T + b  -> bf16          (N=128)
    gemm_bf16<3><<<dim3(2, ROWS/128), 256>>>(p_h1bf, p_Wqkv + 2*Dc*Dc, b_qkv + 2*Dc, nullptr, p_Vbf, ROWS, 128, 128, nullptr);
    // 4) attention (tensor cores, writes O bf16)
    attn_mma<<<dim3(Tc/64, NHc, Sc), 128>>>();
    // 5) y = O @ W_o^T + b_o (fp32)          (N=128)
    gemm_bf16<0><<<dim3(2, ROWS/128), 256>>>(p_Obf, p_Wo, b_o, p_y, nullptr, ROWS, 128, 128, nullptr);
    // 6) h2, LN2 -> h3 (bf16), seed rowsums
    k4b_add_ln<<<ROWS, 128>>>(gamma2, beta2);
    // 7) g = gelu(h3 @ W1^T + b1) (bf16)     (N=512)
    gemm_bf16<1><<<dim3(8, ROWS/128), 256>>>(p_h3bf, p_W1, b1, nullptr, p_gbf, ROWS, 512, 128, nullptr);
    // 8) rowsum(g @ W2^T + b2) -> ysum       (N=128, K=512)
    gemm_bf16<2><<<dim3(2, ROWS/128), 256>>>(p_gbf, p_W2, b2, nullptr, nullptr, ROWS, 128, 512, p_ysum);
    // 9) final combine
    k7_final<<<Bc*Tc, 128>>>(x, W_in, b_in, W_out, b_out, out);
}

// round 9
// speedup vs baseline: 6.8812x; 1.2854x over previous
#include <cuda_runtime.h>
#include <cuda_bf16.h>
#include <math.h>
#include <stdint.h>

// Problem constants
#define Bc   4
#define Tc   512
#define Fc   32
#define Dc   128
#define NHc  4
#define HDc  32
#define WINc 64
#define HIDc 512
#define Sc   (Bc*Fc)          // 128 sequences
#define ROWS (Sc*Tc)          // 65536 rows

// ---------------- scratch (device globals; no allocation) ----------------
__device__ float g_hcf[ROWS*Dc];
__device__ float g_y  [ROWS*Dc];
__device__ float g_ysum[ROWS];

__device__ __nv_bfloat16 g_h1bf[ROWS*Dc];
__device__ __nv_bfloat16 g_qkbf[ROWS*Dc];
__device__ __nv_bfloat16 g_QKo [ROWS*2*Dc];
__device__ __nv_bfloat16 g_Vbf [ROWS*Dc];
__device__ __nv_bfloat16 g_Obf [ROWS*Dc];
__device__ __nv_bfloat16 g_h3bf[ROWS*Dc];
__device__ __nv_bfloat16 g_gbf [ROWS*HIDc];

__device__ __nv_bfloat16 g_Wqkv_bf[3*Dc*Dc];
__device__ __nv_bfloat16 g_Wo_bf  [Dc*Dc];
__device__ __nv_bfloat16 g_W1_bf  [HIDc*Dc];
__device__ __nv_bfloat16 g_W2_bf  [Dc*HIDc];

__device__ __forceinline__ uint32_t smem_u32(const void* p) {
    return (uint32_t)__cvta_generic_to_shared(p);
}
__device__ __forceinline__ void cp16(uint32_t s, const void* g) {
    asm volatile("cp.async.cg.shared.global [%0], [%1], 16;" :: "r"(s), "l"(g));
}

// ---------------- weight conversion ----------------
__global__ void conv_weights(const float* __restrict__ Wqkv,
                             const float* __restrict__ Wo,
                             const float* __restrict__ W1,
                             const float* __restrict__ W2) {
    int i = blockIdx.x*blockDim.x + threadIdx.x;
    if (i < 3*Dc*Dc)  g_Wqkv_bf[i] = __float2bfloat16(Wqkv[i]);
    if (i < Dc*Dc)    g_Wo_bf[i]   = __float2bfloat16(Wo[i]);
    if (i < HIDc*Dc)  g_W1_bf[i]   = __float2bfloat16(W1[i]);
    if (i < Dc*HIDc)  g_W2_bf[i]   = __float2bfloat16(W2[i]);
}

// ---------------- warp reduce over 32 lanes ----------------
__device__ __forceinline__ float warp_sum(float v) {
    #pragma unroll
    for (int o = 16; o; o >>= 1) v += __shfl_xor_sync(0xffffffffu, v, o);
    return v;
}

// ---------------- K1: hcf + LN1 + RoPE  (warp-per-row, no bars) -------------
__global__ __launch_bounds__(128) void k1_hcf_ln_rope(
        const float* __restrict__ x,
        const float* __restrict__ W_in,
        const float* __restrict__ b_in,
        const float* __restrict__ gamma1,
        const float* __restrict__ beta1) {
    const int warp = threadIdx.x >> 5, lane = threadIdx.x & 31;
    const int row = blockIdx.x*4 + warp;       // s*T + t
    const int s = row >> 9, t = row & (Tc-1);
    const int b = s >> 5, f = s & (Fc-1);
    const int d0 = lane*4;

    float xv = __ldg(&x[(b*Tc + t)*Fc + f]);   // warp-uniform broadcast
    float4 bi = *(const float4*)&b_in[d0];
    float hv[4];
    hv[0] = xv * __ldg(&W_in[(d0+0)*Fc + f]) + bi.x;
    hv[1] = xv * __ldg(&W_in[(d0+1)*Fc + f]) + bi.y;
    hv[2] = xv * __ldg(&W_in[(d0+2)*Fc + f]) + bi.z;
    hv[3] = xv * __ldg(&W_in[(d0+3)*Fc + f]) + bi.w;

    float mean = warp_sum(hv[0]+hv[1]+hv[2]+hv[3]) * (1.f/Dc);
    float dv[4];
    float vs = 0.f;
    #pragma unroll
    for (int i=0;i<4;i++) { dv[i] = hv[i]-mean; vs += dv[i]*dv[i]; }
    float var = warp_sum(vs) * (1.f/Dc);
    float rstd = rsqrtf(var + 1e-5f);

    float4 g4 = *(const float4*)&gamma1[d0];
    float4 be4 = *(const float4*)&beta1[d0];
    float h1[4];
    h1[0] = dv[0]*rstd*g4.x + be4.x;
    h1[1] = dv[1]*rstd*g4.y + be4.y;
    h1[2] = dv[2]*rstd*g4.z + be4.z;
    h1[3] = dv[3]*rstd*g4.w + be4.w;

    size_t base = (size_t)row*Dc + d0;
    *(float4*)&g_hcf[base] = make_float4(hv[0],hv[1],hv[2],hv[3]);
    __nv_bfloat162 hb[2];
    hb[0] = __floats2bfloat162_rn(h1[0], h1[1]);
    hb[1] = __floats2bfloat162_rn(h1[2], h1[3]);
    *(uint2*)&g_h1bf[base] = *(uint2*)hb;

    // RoPE: pairs (d0,d0+1),(d0+2,d0+3) are within-thread
    float q[4];
    #pragma unroll
    for (int j=0;j<2;j++) {
        int hd = (d0 + 2*j) & (HDc-1);
        int i2 = hd >> 1;
        float inv = __expf(-(float)(2*i2) * (9.210340371976184f / (float)HDc));
        float fr = (float)t * inv;
        float sn, cs;
        __sincosf(fr, &sn, &cs);
        float e = h1[2*j], o = h1[2*j+1];
        q[2*j]   = e*cs - o*sn;
        q[2*j+1] = e*sn + o*cs;
    }
    __nv_bfloat162 qb[2];
    qb[0] = __floats2bfloat162_rn(q[0], q[1]);
    qb[1] = __floats2bfloat162_rn(q[2], q[3]);
    *(uint2*)&g_qkbf[base] = *(uint2*)qb;
}

// ---------------- bf16 tensor-core GEMM (cp.async double-buffered) -----------
// EPI 0: Cf = acc+bias ; EPI 1: Cbf = gelu ; EPI 2: rowsum->atomicAdd ; EPI 3: Cbf
#define PKS 40

template<int EPI>
__global__ __launch_bounds__(256) void gemm_bf16(
    const __nv_bfloat16* __restrict__ A,
    const __nv_bfloat16* __restrict__ B,
    const float* __restrict__ bias,
    float* __restrict__ Cf,
    __nv_bfloat16* __restrict__ Cbf,
    int M, int N, int K,
    float* __restrict__ rowsum)
{
    __shared__ __nv_bfloat16 As[2][128*PKS];
    __shared__ __nv_bfloat16 Bs[2][64*PKS];
    const int bm = blockIdx.y * 128;
    const int bn = blockIdx.x * 64;
    const int tid  = threadIdx.x;
    const int warp = tid >> 5, lane = tid & 31;
    const int wm = warp >> 1;
    const int wn = warp & 1;

    float acc[2][4][4];
    #pragma unroll
    for (int mi=0;mi<2;mi++)
        #pragma unroll
        for (int ni=0;ni<4;ni++)
            #pragma unroll
            for (int j=0;j<4;j++) acc[mi][ni][j] = 0.f;

    const int lrow = tid >> 2;
    const int lcol = (tid & 3) * 8;
    const int niter = K >> 5;

    // preload stage 0
    cp16(smem_u32(&As[0][lrow*PKS + lcol]),      &A[(size_t)(bm + lrow)*K + lcol]);
    cp16(smem_u32(&As[0][(64+lrow)*PKS + lcol]), &A[(size_t)(bm + 64 + lrow)*K + lcol]);
    cp16(smem_u32(&Bs[0][lrow*PKS + lcol]),      &B[(size_t)(bn + lrow)*K + lcol]);
    asm volatile("cp.async.commit_group;");

    for (int it = 0; it < niter; it++) {
        if (it + 1 < niter) {
            int k0 = (it+1) << 5, st = (it+1) & 1;
            cp16(smem_u32(&As[st][lrow*PKS + lcol]),      &A[(size_t)(bm + lrow)*K + k0 + lcol]);
            cp16(smem_u32(&As[st][(64+lrow)*PKS + lcol]), &A[(size_t)(bm + 64 + lrow)*K + k0 + lcol]);
            cp16(smem_u32(&Bs[st][lrow*PKS + lcol]),      &B[(size_t)(bn + lrow)*K + k0 + lcol]);
            asm volatile("cp.async.commit_group;");
            asm volatile("cp.async.wait_group 1;");
        } else {
            asm volatile("cp.async.wait_group 0;");
        }
        __syncthreads();
        const int cur = it & 1;

        #pragma unroll
        for (int ks = 0; ks < 2; ks++) {
            uint32_t af[2][4], bfr[4][2];
            #pragma unroll
            for (int mi=0;mi<2;mi++) {
                int row = wm*32 + mi*16 + (lane & 15);
                int col = ks*16 + (lane >> 4)*8;
                uint32_t addr = smem_u32(&As[cur][row*PKS + col]);
                asm volatile("ldmatrix.sync.aligned.m8n8.x4.shared.b16 {%0,%1,%2,%3}, [%4];"
                    : "=r"(af[mi][0]),"=r"(af[mi][1]),"=r"(af[mi][2]),"=r"(af[mi][3])
                    : "r"(addr));
            }
            #pragma unroll
            for (int ni=0;ni<4;ni++) {
                int row = wn*32 + ni*8 + (lane & 7);
                int col = ks*16 + ((lane >> 3)&1)*8;
                uint32_t addr = smem_u32(&Bs[cur][row*PKS + col]);
                asm volatile("ldmatrix.sync.aligned.m8n8.x2.shared.b16 {%0,%1}, [%2];"
                    : "=r"(bfr[ni][0]),"=r"(bfr[ni][1]) : "r"(addr));
            }
            #pragma unroll
            for (int mi=0;mi<2;mi++)
                #pragma unroll
                for (int ni=0;ni<4;ni++)
                    asm volatile("mma.sync.aligned.m16n8k16.row.col.f32.bf16.bf16.f32 "
                        "{%0,%1,%2,%3}, {%4,%5,%6,%7}, {%8,%9}, {%0,%1,%2,%3};"
                        : "+f"(acc[mi][ni][0]),"+f"(acc[mi][ni][1]),
                          "+f"(acc[mi][ni][2]),"+f"(acc[mi][ni][3])
                        : "r"(af[mi][0]),"r"(af[mi][1]),"r"(af[mi][2]),"r"(af[mi][3]),
                          "r"(bfr[ni][0]),"r"(bfr[ni][1]));
        }
        __syncthreads();
    }

    // ---------------- epilogue ----------------
    if (EPI == 2) {
        #pragma unroll
        for (int mi=0;mi<2;mi++) {
            float s0 = 0.f, s1 = 0.f;
            #pragma unroll
            for (int ni=0;ni<4;ni++) {
                int c = bn + wn*32 + ni*8 + (lane&3)*2;
                float b0v = bias[c], b1v = bias[c+1];
                s0 += acc[mi][ni][0] + b0v + acc[mi][ni][1] + b1v;
                s1 += acc[mi][ni][2] + b0v + acc[mi][ni][3] + b1v;
            }
            s0 += __shfl_xor_sync(0xffffffffu, s0, 1);
            s0 += __shfl_xor_sync(0xffffffffu, s0, 2);
            s1 += __shfl_xor_sync(0xffffffffu, s1, 1);
            s1 += __shfl_xor_sync(0xffffffffu, s1, 2);
            if ((lane&3) == 0) {
                int r = bm + wm*32 + mi*16 + (lane>>2);
                atomicAdd(&rowsum[r],     s0);
                atomicAdd(&rowsum[r+8],   s1);
            }
        }
    } else {
        #pragma unroll
        for (int mi=0;mi<2;mi++) {
            int r0 = bm + wm*32 + mi*16 + (lane>>2);
            #pragma unroll
            for (int ni=0;ni<4;ni++) {
                int c = bn + wn*32 + ni*8 + (lane&3)*2;
                float v0 = acc[mi][ni][0] + bias[c];
                float v1 = acc[mi][ni][1] + bias[c+1];
                float v2 = acc[mi][ni][2] + bias[c];
                float v3 = acc[mi][ni][3] + bias[c+1];
                if (EPI == 1) {
                    v0 = 0.5f*v0*(1.f + erff(v0*0.7071067811865476f));
                    v1 = 0.5f*v1*(1.f + erff(v1*0.7071067811865476f));
                    v2 = 0.5f*v2*(1.f + erff(v2*0.7071067811865476f));
                    v3 = 0.5f*v3*(1.f + erff(v3*0.7071067811865476f));
                }
                if (EPI == 1 || EPI == 3) {
                    __nv_bfloat162 p0 = __floats2bfloat162_rn(v0, v1);
                    __nv_bfloat162 p1 = __floats2bfloat162_rn(v2, v3);
                    *(__nv_bfloat162*)&Cbf[(size_t)r0*N + c]     = p0;
                    *(__nv_bfloat162*)&Cbf[(size_t)(r0+8)*N + c] = p1;
                } else {
                    *(float2*)&Cf[(size_t)r0*N + c]     = make_float2(v0, v1);
                    *(float2*)&Cf[(size_t)(r0+8)*N + c] = make_float2(v2, v3);
                }
            }
        }
    }
}

// ---------------- Attention: tensor-core, windowed causal ----------------
#define QPAD 40

__global__ __launch_bounds__(128) void attn_mma() {
    __shared__ __nv_bfloat16 Qs[64*QPAD];
    __shared__ __nv_bfloat16 Ks[128*QPAD];
    __shared__ __nv_bfloat16 Vs[128*QPAD];   // row-major [key][hd]
    const int qtile = blockIdx.x, h = blockIdx.y, s = blockIdx.z;
    const int q0 = qtile*64;
    const int tid = threadIdx.x, warp = tid>>5, lane = tid&31;

    for (int i = tid; i < 64*4; i += 128) {
        int r = i>>2, c4 = (i&3)*8;
        *(uint4*)&Qs[r*QPAD + c4] =
            *(const uint4*)&g_QKo[(size_t)(s*Tc + q0 + r)*(2*Dc) + h*HDc + c4];
    }
    for (int i = tid; i < 128*4; i += 128) {
        int r = i>>2, c4 = (i&3)*8;
        int kt = q0 - 64 + r;
        uint4 kval = make_uint4(0,0,0,0), vval = make_uint4(0,0,0,0);
        if (kt >= 0) {
            kval = *(const uint4*)&g_QKo[(size_t)(s*Tc + kt)*(2*Dc) + Dc + h*HDc + c4];
            vval = *(const uint4*)&g_Vbf[(size_t)(s*Tc + kt)*Dc + h*HDc + c4];
        }
        *(uint4*)&Ks[r*QPAD + c4] = kval;
        *(uint4*)&Vs[r*QPAD + c4] = vval;
    }
    __syncthreads();

    // Q A-fragments
    uint32_t aq[2][4];
    #pragma unroll
    for (int kk=0; kk<2; kk++) {
        int row = warp*16 + (lane & 15);
        int col = kk*16 + (lane >> 4)*8;
        uint32_t addr = smem_u32(&Qs[row*QPAD + col]);
        asm volatile("ldmatrix.sync.aligned.m8n8.x4.shared.b16 {%0,%1,%2,%3}, [%4];"
            : "=r"(aq[kk][0]),"=r"(aq[kk][1]),"=r"(aq[kk][2]),"=r"(aq[kk][3])
            : "r"(addr));
    }

    // S = Q K^T
    float sc[16][4];
    #pragma unroll
    for (int ni=0; ni<16; ni++) { sc[ni][0]=sc[ni][1]=sc[ni][2]=sc[ni][3]=0.f; }
    #pragma unroll
    for (int ni=0; ni<16; ni++) {
        #pragma unroll
        for (int kk=0; kk<2; kk++) {
            uint32_t b0, b1;
            int row = ni*8 + (lane & 7);
            int col = kk*16 + ((lane >> 3)&1)*8;
            uint32_t addr = smem_u32(&Ks[row*QPAD + col]);
            asm volatile("ldmatrix.sync.aligned.m8n8.x2.shared.b16 {%0,%1}, [%2];"
                : "=r"(b0),"=r"(b1) : "r"(addr));
            asm volatile("mma.sync.aligned.m16n8k16.row.col.f32.bf16.bf16.f32 "
                "{%0,%1,%2,%3}, {%4,%5,%6,%7}, {%8,%9}, {%0,%1,%2,%3};"
                : "+f"(sc[ni][0]),"+f"(sc[ni][1]),"+f"(sc[ni][2]),"+f"(sc[ni][3])
                : "r"(aq[kk][0]),"r"(aq[kk][1]),"r"(aq[kk][2]),"r"(aq[kk][3]),
                  "r"(b0),"r"(b1));
        }
    }

    // mask + softmax
    const float scale = 0.17677669529663687f;
    const int g = lane >> 2, t4 = lane & 3;
    const int qg0 = q0 + warp*16 + g;
    const int qg1 = qg0 + 8;
    float mx0 = -INFINITY, mx1 = -INFINITY;
    #pragma unroll
    for (int ni=0; ni<16; ni++) {
        #pragma unroll
        for (int j=0; j<2; j++) {
            int col = ni*8 + 2*t4 + j;
            int kg = q0 - 64 + col;
            float v0 = sc[ni][j]   * scale;
            float v1 = sc[ni][2+j] * scale;
            bool ok0 = (kg >= 0) && (kg <= qg0) && (qg0 - kg <= WINc);
            bool ok1 = (kg >= 0) && (kg <= qg1) && (qg1 - kg <= WINc);
            sc[ni][j]   = ok0 ? v0 : -INFINITY;
            sc[ni][2+j] = ok1 ? v1 : -INFINITY;
            mx0 = fmaxf(mx0, sc[ni][j]);
            mx1 = fmaxf(mx1, sc[ni][2+j]);
        }
    }
    mx0 = fmaxf(mx0, __shfl_xor_sync(0xffffffffu, mx0, 1));
    mx0 = fmaxf(mx0, __shfl_xor_sync(0xffffffffu, mx0, 2));
    mx1 = fmaxf(mx1, __shfl_xor_sync(0xffffffffu, mx1, 1));
    mx1 = fmaxf(mx1, __shfl_xor_sync(0xffffffffu, mx1, 2));
    float sum0 = 0.f, sum1 = 0.f;
    #pragma unroll
    for (int ni=0; ni<16; ni++) {
        #pragma unroll
        for (int j=0; j<2; j++) {
            float e0 = (sc[ni][j]   > -INFINITY) ? __expf(sc[ni][j]   - mx0) : 0.f;
            float e1 = (sc[ni][2+j] > -INFINITY) ? __expf(sc[ni][2+j] - mx1) : 0.f;
            sc[ni][j] = e0; sc[ni][2+j] = e1;
            sum0 += e0; sum1 += e1;
        }
    }
    sum0 += __shfl_xor_sync(0xffffffffu, sum0, 1);
    sum0 += __shfl_xor_sync(0xffffffffu, sum0, 2);
    sum1 += __shfl_xor_sync(0xffffffffu, sum1, 1);
    sum1 += __shfl_xor_sync(0xffffffffu, sum1, 2);
    float inv0 = 1.f/sum0, inv1 = 1.f/sum1;

    // pack P into A-fragments
    uint32_t pa[8][4];
    #pragma unroll
    for (int kt8=0; kt8<8; kt8++) {
        __nv_bfloat162 t0 = __floats2bfloat162_rn(sc[2*kt8][0]*inv0,   sc[2*kt8][1]*inv0);
        __nv_bfloat162 t1 = __floats2bfloat162_rn(sc[2*kt8][2]*inv1,   sc[2*kt8][3]*inv1);
        __nv_bfloat162 t2 = __floats2bfloat162_rn(sc[2*kt8+1][0]*inv0, sc[2*kt8+1][1]*inv0);
        __nv_bfloat162 t3 = __floats2bfloat162_rn(sc[2*kt8+1][2]*inv1, sc[2*kt8+1][3]*inv1);
        pa[kt8][0] = *(uint32_t*)&t0;
        pa[kt8][1] = *(uint32_t*)&t1;
        pa[kt8][2] = *(uint32_t*)&t2;
        pa[kt8][3] = *(uint32_t*)&t3;
    }

    // O = P V : B-fragments via ldmatrix.trans on row-major V[key][hd]
    float oacc[4][4];
    #pragma unroll
    for (int ni=0; ni<4; ni++) { oacc[ni][0]=oacc[ni][1]=oacc[ni][2]=oacc[ni][3]=0.f; }
    #pragma unroll
    for (int kt8=0; kt8<8; kt8++) {
        #pragma unroll
        for (int ni=0; ni<4; ni++) {
            uint32_t b0, b1;
            int row = kt8*16 + ((lane >> 3)&1)*8 + (lane & 7);
            int col = ni*8;
            uint32_t addr = smem_u32(&Vs[row*QPAD + col]);
            asm volatile("ldmatrix.sync.aligned.m8n8.x2.trans.shared.b16 {%0,%1}, [%2];"
                : "=r"(b0),"=r"(b1) : "r"(addr));
            asm volatile("mma.sync.aligned.m16n8k16.row.col.f32.bf16.bf16.f32 "
                "{%0,%1,%2,%3}, {%4,%5,%6,%7}, {%8,%9}, {%0,%1,%2,%3};"
                : "+f"(oacc[ni][0]),"+f"(oacc[ni][1]),"+f"(oacc[ni][2]),"+f"(oacc[ni][3])
                : "r"(pa[kt8][0]),"r"(pa[kt8][1]),"r"(pa[kt8][2]),"r"(pa[kt8][3]),
                  "r"(b0),"r"(b1));
        }
    }

    #pragma unroll
    for (int ni=0; ni<4; ni++) {
        int col = ni*8 + 2*t4;
        __nv_bfloat162 p0 = __floats2bfloat162_rn(oacc[ni][0], oacc[ni][1]);
        __nv_bfloat162 p1 = __floats2bfloat162_rn(oacc[ni][2], oacc[ni][3]);
        *(__nv_bfloat162*)&g_Obf[(size_t)(s*Tc + qg0)*Dc + h*HDc + col] = p0;
        *(__nv_bfloat162*)&g_Obf[(size_t)(s*Tc + qg1)*Dc + h*HDc + col] = p1;
    }
}

// ---------------- K4b: h2 = hcf + y ; LN2 -> h3(bf16) (warp-per-row) --------
__global__ __launch_bounds__(128) void k4b_add_ln(
        const float* __restrict__ gamma2,
        const float* __restrict__ beta2) {
    const int warp = threadIdx.x >> 5, lane = threadIdx.x & 31;
    const int row = blockIdx.x*4 + warp;
    const int d0 = lane*4;
    size_t base = (size_t)row*Dc + d0;

    float4 hc = *(const float4*)&g_hcf[base];
    float4 yv = *(const float4*)&g_y[base];
    float h2[4] = {hc.x+yv.x, hc.y+yv.y, hc.z+yv.z, hc.w+yv.w};

    float tot = warp_sum(h2[0]+h2[1]+h2[2]+h2[3]);
    float mean = tot * (1.f/Dc);
    float dv[4], vs = 0.f;
    #pragma unroll
    for (int i=0;i<4;i++) { dv[i] = h2[i]-mean; vs += dv[i]*dv[i]; }
    float var = warp_sum(vs) * (1.f/Dc);
    float rstd = rsqrtf(var + 1e-5f);

    float4 g4 = *(const float4*)&gamma2[d0];
    float4 b4 = *(const float4*)&beta2[d0];
    __nv_bfloat162 hb[2];
    hb[0] = __floats2bfloat162_rn(dv[0]*rstd*g4.x + b4.x, dv[1]*rstd*g4.y + b4.y);
    hb[1] = __floats2bfloat162_rn(dv[2]*rstd*g4.z + b4.z, dv[3]*rstd*g4.w + b4.w);
    *(uint2*)&g_h3bf[base] = *(uint2*)hb;
    if (lane == 0) g_ysum[row] = tot;   // sum(h2 row)
}

// ---------------- K7: final combine ----------------
__global__ void k7_final(const float* __restrict__ x,
                         const float* __restrict__ W_in,
                         const float* __restrict__ b_in,
                         const float* __restrict__ W_out,
                         const float* __restrict__ b_out,
                         float* __restrict__ out) {
    __shared__ float xs[Fc];
    __shared__ float xw[Dc];
    int bt = blockIdx.x;               // b*T + t
    int tid = threadIdx.x;             // 128
    if (tid < Fc) xs[tid] = x[bt*Fc + tid];
    __syncthreads();
    float acc = b_in[tid];
    #pragma unroll
    for (int f=0; f<Fc; f++) acc += xs[f]*W_in[tid*Fc + f];
    xw[tid] = acc;
    __syncthreads();
    if (tid < Fc) {
        float yp = b_out[tid];
        for (int dd=0; dd<Dc; dd++) yp += xw[dd]*W_out[tid*Dc + dd];
        int b = bt >> 9, t = bt & (Tc-1);
        int srow = (b*Fc + tid)*Tc + t;
        float ymean = g_ysum[srow] * (1.f/(float)Dc);
        out[bt*Fc + tid] = xs[tid] + ymean + yp;
    }
}

// ---------------- launcher ----------------
extern "C" void kernel_launch(void* const* d_in, const int* in_sizes, int n_in,
                              void* d_out, int out_size) {
    const float* x      = (const float*)d_in[0];
    const float* W_in   = (const float*)d_in[1];
    const float* b_in   = (const float*)d_in[2];
    const float* gamma1 = (const float*)d_in[3];
    const float* beta1  = (const float*)d_in[4];
    const float* gamma2 = (const float*)d_in[5];
    const float* beta2  = (const float*)d_in[6];
    const float* W_qkv  = (const float*)d_in[7];
    const float* b_qkv  = (const float*)d_in[8];
    const float* W_o    = (const float*)d_in[9];
    const float* b_o    = (const float*)d_in[10];
    const float* W1     = (const float*)d_in[11];
    const float* b1     = (const float*)d_in[12];
    const float* W2     = (const float*)d_in[13];
    const float* b2     = (const float*)d_in[14];
    const float* W_out  = (const float*)d_in[15];
    const float* b_out  = (const float*)d_in[16];
    float* out = (float*)d_out;

    float *p_y, *p_ysum;
    __nv_bfloat16 *p_h1bf, *p_qkbf, *p_QKo, *p_Vbf, *p_Obf, *p_h3bf, *p_gbf;
    __nv_bfloat16 *p_Wqkv, *p_Wo, *p_W1, *p_W2;
    cudaGetSymbolAddress((void**)&p_y,    g_y);
    cudaGetSymbolAddress((void**)&p_ysum, g_ysum);
    cudaGetSymbolAddress((void**)&p_h1bf, g_h1bf);
    cudaGetSymbolAddress((void**)&p_qkbf, g_qkbf);
    cudaGetSymbolAddress((void**)&p_QKo,  g_QKo);
    cudaGetSymbolAddress((void**)&p_Vbf,  g_Vbf);
    cudaGetSymbolAddress((void**)&p_Obf,  g_Obf);
    cudaGetSymbolAddress((void**)&p_h3bf, g_h3bf);
    cudaGetSymbolAddress((void**)&p_gbf,  g_gbf);
    cudaGetSymbolAddress((void**)&p_Wqkv, g_Wqkv_bf);
    cudaGetSymbolAddress((void**)&p_Wo,   g_Wo_bf);
    cudaGetSymbolAddress((void**)&p_W1,   g_W1_bf);
    cudaGetSymbolAddress((void**)&p_W2,   g_W2_bf);

    // 0) weights -> bf16
    conv_weights<<<(HIDc*Dc + 255)/256, 256>>>(W_qkv, W_o, W1, W2);
    // 1) hcf + LN1 + RoPE
    k1_hcf_ln_rope<<<ROWS/4, 128>>>(x, W_in, b_in, gamma1, beta1);
    // 2) Q,K -> bf16   (N=256)
    gemm_bf16<3><<<dim3(4, ROWS/128), 256>>>(p_qkbf, p_Wqkv, b_qkv, nullptr, p_QKo, ROWS, 256, 128, nullptr);
    // 3) V -> bf16     (N=128)
    gemm_bf16<3><<<dim3(2, ROWS/128), 256>>>(p_h1bf, p_Wqkv + 2*Dc*Dc, b_qkv + 2*Dc, nullptr, p_Vbf, ROWS, 128, 128, nullptr);
    // 4) attention
    attn_mma<<<dim3(Tc/64, NHc, Sc), 128>>>();
    // 5) y = O @ W_o^T + b_o (fp32)
    gemm_bf16<0><<<dim3(2, ROWS/128), 256>>>(p_Obf, p_Wo, b_o, p_y, nullptr, ROWS, 128, 128, nullptr);
    // 6) h2, LN2 -> h3 (bf16), seed rowsums
    k4b_add_ln<<<ROWS/4, 128>>>(gamma2, beta2);
    // 7) g = gelu(...) (bf16)  (N=512)
    gemm_bf16<1><<<dim3(8, ROWS/128), 256>>>(p_h3bf, p_W1, b1, nullptr, p_gbf, ROWS, 512, 128, nullptr);
    // 8) rowsum epilogue       (N=128, K=512)
    gemm_bf16<2><<<dim3(2, ROWS/128), 256>>>(p_gbf, p_W2, b2, nullptr, nullptr, ROWS, 128, 512, p_ysum);
    // 9) final combine
    k7_final<<<Bc*Tc, 128>>>(x, W_in, b_in, W_out, b_out, out);
}

// round 11
// speedup vs baseline: 7.3421x; 1.0670x over previous
#include <cuda_runtime.h>
#include <cuda_bf16.h>
#include <math.h>
#include <stdint.h>

// Problem constants
#define Bc   4
#define Tc   512
#define Fc   32
#define Dc   128
#define NHc  4
#define HDc  32
#define WINc 64
#define HIDc 512
#define Sc   (Bc*Fc)          // 128 sequences
#define ROWS (Sc*Tc)          // 65536 rows

// ---------------- scratch (device globals; no allocation) ----------------
__device__ float g_hcf[ROWS*Dc];
__device__ float g_y  [ROWS*Dc];        // holds h2 after Wo gemm (EPI 4)
__device__ float g_ysum[ROWS];
__device__ float g_w2sum[HIDc];
__device__ float g_b2sum;

__device__ __nv_bfloat16 g_h1bf[ROWS*Dc];
__device__ __nv_bfloat16 g_qkbf[ROWS*Dc];
__device__ __nv_bfloat16 g_QKo [ROWS*2*Dc];
__device__ __nv_bfloat16 g_Vbf [ROWS*Dc];
__device__ __nv_bfloat16 g_Obf [ROWS*Dc];
__device__ __nv_bfloat16 g_h3bf[ROWS*Dc];

__device__ __nv_bfloat16 g_Wqkv_bf[3*Dc*Dc];
__device__ __nv_bfloat16 g_Wo_bf  [Dc*Dc];
__device__ __nv_bfloat16 g_W1_bf  [HIDc*Dc];

__device__ __forceinline__ uint32_t smem_u32(const void* p) {
    return (uint32_t)__cvta_generic_to_shared(p);
}
__device__ __forceinline__ void cp16(uint32_t s, const void* g) {
    asm volatile("cp.async.cg.shared.global [%0], [%1], 16;" :: "r"(s), "l"(g));
}

// ---------------- weight prep: bf16 conversion + w2sum/b2sum ----------------
__global__ void conv_weights(const float* __restrict__ Wqkv,
                             const float* __restrict__ Wo,
                             const float* __restrict__ W1,
                             const float* __restrict__ W2,
                             const float* __restrict__ b2) {
    int i = blockIdx.x*blockDim.x + threadIdx.x;
    if (i < 3*Dc*Dc)  g_Wqkv_bf[i] = __float2bfloat16(Wqkv[i]);
    if (i < Dc*Dc)    g_Wo_bf[i]   = __float2bfloat16(Wo[i]);
    if (i < HIDc*Dc)  g_W1_bf[i]   = __float2bfloat16(W1[i]);
    if (i < HIDc) {                     // w2sum[k] = sum_d W2[d,k]
        float s = 0.f;
        #pragma unroll 4
        for (int n = 0; n < Dc; n++) s += W2[n*HIDc + i];
        g_w2sum[i] = s;
    }
    if (i == 0) {
        float s = 0.f;
        for (int d = 0; d < Dc; d++) s += b2[d];
        g_b2sum = s;
    }
}

// ---------------- warp reduce over 32 lanes ----------------
__device__ __forceinline__ float warp_sum(float v) {
    #pragma unroll
    for (int o = 16; o; o >>= 1) v += __shfl_xor_sync(0xffffffffu, v, o);
    return v;
}

// ---------------- K1: hcf + LN1 + RoPE  (warp-per-row, no bars) -------------
__global__ __launch_bounds__(128) void k1_hcf_ln_rope(
        const float* __restrict__ x,
        const float* __restrict__ W_in,
        const float* __restrict__ b_in,
        const float* __restrict__ gamma1,
        const float* __restrict__ beta1) {
    const int warp = threadIdx.x >> 5, lane = threadIdx.x & 31;
    const int row = blockIdx.x*4 + warp;       // s*T + t
    const int s = row >> 9, t = row & (Tc-1);
    const int b = s >> 5, f = s & (Fc-1);
    const int d0 = lane*4;

    float xv = __ldg(&x[(b*Tc + t)*Fc + f]);
    float4 bi = *(const float4*)&b_in[d0];
    float hv[4];
    hv[0] = xv * __ldg(&W_in[(d0+0)*Fc + f]) + bi.x;
    hv[1] = xv * __ldg(&W_in[(d0+1)*Fc + f]) + bi.y;
    hv[2] = xv * __ldg(&W_in[(d0+2)*Fc + f]) + bi.z;
    hv[3] = xv * __ldg(&W_in[(d0+3)*Fc + f]) + bi.w;

    float mean = warp_sum(hv[0]+hv[1]+hv[2]+hv[3]) * (1.f/Dc);
    float dv[4];
    float vs = 0.f;
    #pragma unroll
    for (int i=0;i<4;i++) { dv[i] = hv[i]-mean; vs += dv[i]*dv[i]; }
    float var = warp_sum(vs) * (1.f/Dc);
    float rstd = rsqrtf(var + 1e-5f);

    float4 g4 = *(const float4*)&gamma1[d0];
    float4 be4 = *(const float4*)&beta1[d0];
    float h1[4];
    h1[0] = dv[0]*rstd*g4.x + be4.x;
    h1[1] = dv[1]*rstd*g4.y + be4.y;
    h1[2] = dv[2]*rstd*g4.z + be4.z;
    h1[3] = dv[3]*rstd*g4.w + be4.w;

    size_t base = (size_t)row*Dc + d0;
    *(float4*)&g_hcf[base] = make_float4(hv[0],hv[1],hv[2],hv[3]);
    __nv_bfloat162 hb[2];
    hb[0] = __floats2bfloat162_rn(h1[0], h1[1]);
    hb[1] = __floats2bfloat162_rn(h1[2], h1[3]);
    *(uint2*)&g_h1bf[base] = *(uint2*)hb;

    // RoPE
    float q[4];
    #pragma unroll
    for (int j=0;j<2;j++) {
        int hd = (d0 + 2*j) & (HDc-1);
        int i2 = hd >> 1;
        float inv = __expf(-(float)(2*i2) * (9.210340371976184f / (float)HDc));
        float fr = (float)t * inv;
        float sn, cs;
        __sincosf(fr, &sn, &cs);
        float e = h1[2*j], o = h1[2*j+1];
        q[2*j]   = e*cs - o*sn;
        q[2*j+1] = e*sn + o*cs;
    }
    __nv_bfloat162 qb[2];
    qb[0] = __floats2bfloat162_rn(q[0], q[1]);
    qb[1] = __floats2bfloat162_rn(q[2], q[3]);
    *(uint2*)&g_qkbf[base] = *(uint2*)qb;
}

// ---------------- bf16 tensor-core GEMM (cp.async double-buffered) -----------
// EPI 1: gelu(acc+bias)·w2s rowsum -> atomicAdd rowsum[] (no C store)
// EPI 3: Cbf = acc+bias (bf16)
// EPI 4: Cf  = acc+bias+hres (fp32)   [residual-fused]
#define PKS 40

template<int EPI>
__global__ __launch_bounds__(256) void gemm_bf16(
    const __nv_bfloat16* __restrict__ A,
    const __nv_bfloat16* __restrict__ B,
    const float* __restrict__ bias,
    float* __restrict__ Cf,
    __nv_bfloat16* __restrict__ Cbf,
    int M, int N, int K,
    float* __restrict__ rowsum,
    const float* __restrict__ w2s,
    const float* __restrict__ hres)
{
    __shared__ __nv_bfloat16 As[2][128*PKS];
    __shared__ __nv_bfloat16 Bs[2][64*PKS];
    const int bm = blockIdx.y * 128;
    const int bn = blockIdx.x * 64;
    const int tid  = threadIdx.x;
    const int warp = tid >> 5, lane = tid & 31;
    const int wm = warp >> 1;
    const int wn = warp & 1;

    float acc[2][4][4];
    #pragma unroll
    for (int mi=0;mi<2;mi++)
        #pragma unroll
        for (int ni=0;ni<4;ni++)
            #pragma unroll
            for (int j=0;j<4;j++) acc[mi][ni][j] = 0.f;

    const int lrow = tid >> 2;
    const int lcol = (tid & 3) * 8;
    const int niter = K >> 5;

    cp16(smem_u32(&As[0][lrow*PKS + lcol]),      &A[(size_t)(bm + lrow)*K + lcol]);
    cp16(smem_u32(&As[0][(64+lrow)*PKS + lcol]), &A[(size_t)(bm + 64 + lrow)*K + lcol]);
    cp16(smem_u32(&Bs[0][lrow*PKS + lcol]),      &B[(size_t)(bn + lrow)*K + lcol]);
    asm volatile("cp.async.commit_group;");

    for (int it = 0; it < niter; it++) {
        if (it + 1 < niter) {
            int k0 = (it+1) << 5, st = (it+1) & 1;
            cp16(smem_u32(&As[st][lrow*PKS + lcol]),      &A[(size_t)(bm + lrow)*K + k0 + lcol]);
            cp16(smem_u32(&As[st][(64+lrow)*PKS + lcol]), &A[(size_t)(bm + 64 + lrow)*K + k0 + lcol]);
            cp16(smem_u32(&Bs[st][lrow*PKS + lcol]),      &B[(size_t)(bn + lrow)*K + k0 + lcol]);
            asm volatile("cp.async.commit_group;");
            asm volatile("cp.async.wait_group 1;");
        } else {
            asm volatile("cp.async.wait_group 0;");
        }
        __syncthreads();
        const int cur = it & 1;

        #pragma unroll
        for (int ks = 0; ks < 2; ks++) {
            uint32_t af[2][4], bfr[4][2];
            #pragma unroll
            for (int mi=0;mi<2;mi++) {
                int row = wm*32 + mi*16 + (lane & 15);
                int col = ks*16 + (lane >> 4)*8;
                uint32_t addr = smem_u32(&As[cur][row*PKS + col]);
                asm volatile("ldmatrix.sync.aligned.m8n8.x4.shared.b16 {%0,%1,%2,%3}, [%4];"
                    : "=r"(af[mi][0]),"=r"(af[mi][1]),"=r"(af[mi][2]),"=r"(af[mi][3])
                    : "r"(addr));
            }
            #pragma unroll
            for (int ni=0;ni<4;ni++) {
                int row = wn*32 + ni*8 + (lane & 7);
                int col = ks*16 + ((lane >> 3)&1)*8;
                uint32_t addr = smem_u32(&Bs[cur][row*PKS + col]);
                asm volatile("ldmatrix.sync.aligned.m8n8.x2.shared.b16 {%0,%1}, [%2];"
                    : "=r"(bfr[ni][0]),"=r"(bfr[ni][1]) : "r"(addr));
            }
            #pragma unroll
            for (int mi=0;mi<2;mi++)
                #pragma unroll
                for (int ni=0;ni<4;ni++)
                    asm volatile("mma.sync.aligned.m16n8k16.row.col.f32.bf16.bf16.f32 "
                        "{%0,%1,%2,%3}, {%4,%5,%6,%7}, {%8,%9}, {%0,%1,%2,%3};"
                        : "+f"(acc[mi][ni][0]),"+f"(acc[mi][ni][1]),
                          "+f"(acc[mi][ni][2]),"+f"(acc[mi][ni][3])
                        : "r"(af[mi][0]),"r"(af[mi][1]),"r"(af[mi][2]),"r"(af[mi][3]),
                          "r"(bfr[ni][0]),"r"(bfr[ni][1]));
        }
        __syncthreads();
    }

    // ---------------- epilogue ----------------
    if (EPI == 1) {
        // gelu + weighted rowsum (FFN fused: ffn_rowsum += gelu(v)*w2sum[c])
        #pragma unroll
        for (int mi=0;mi<2;mi++) {
            float s0 = 0.f, s1 = 0.f;
            #pragma unroll
            for (int ni=0;ni<4;ni++) {
                int c = bn + wn*32 + ni*8 + (lane&3)*2;
                float b0v = bias[c], b1v = bias[c+1];
                float w0 = w2s[c],  w1 = w2s[c+1];
                float v0 = acc[mi][ni][0] + b0v;
                float v1 = acc[mi][ni][1] + b1v;
                float v2 = acc[mi][ni][2] + b0v;
                float v3 = acc[mi][ni][3] + b1v;
                v0 = 0.5f*v0*(1.f + erff(v0*0.7071067811865476f));
                v1 = 0.5f*v1*(1.f + erff(v1*0.7071067811865476f));
                v2 = 0.5f*v2*(1.f + erff(v2*0.7071067811865476f));
                v3 = 0.5f*v3*(1.f + erff(v3*0.7071067811865476f));
                s0 += v0*w0 + v1*w1;
                s1 += v2*w0 + v3*w1;
            }
            s0 += __shfl_xor_sync(0xffffffffu, s0, 1);
            s0 += __shfl_xor_sync(0xffffffffu, s0, 2);
            s1 += __shfl_xor_sync(0xffffffffu, s1, 1);
            s1 += __shfl_xor_sync(0xffffffffu, s1, 2);
            if ((lane&3) == 0) {
                int r = bm + wm*32 + mi*16 + (lane>>2);
                atomicAdd(&rowsum[r],   s0);
                atomicAdd(&rowsum[r+8], s1);
            }
        }
    } else {
        #pragma unroll
        for (int mi=0;mi<2;mi++) {
            int r0 = bm + wm*32 + mi*16 + (lane>>2);
            #pragma unroll
            for (int ni=0;ni<4;ni++) {
                int c = bn + wn*32 + ni*8 + (lane&3)*2;
                float v0 = acc[mi][ni][0] + bias[c];
                float v1 = acc[mi][ni][1] + bias[c+1];
                float v2 = acc[mi][ni][2] + bias[c];
                float v3 = acc[mi][ni][3] + bias[c+1];
                if (EPI == 3) {
                    __nv_bfloat162 p0 = __floats2bfloat162_rn(v0, v1);
                    __nv_bfloat162 p1 = __floats2bfloat162_rn(v2, v3);
                    *(__nv_bfloat162*)&Cbf[(size_t)r0*N + c]     = p0;
                    *(__nv_bfloat162*)&Cbf[(size_t)(r0+8)*N + c] = p1;
                } else { // EPI 4: + residual hres
                    float2 h0 = *(const float2*)&hres[(size_t)r0*N + c];
                    float2 h1 = *(const float2*)&hres[(size_t)(r0+8)*N + c];
                    *(float2*)&Cf[(size_t)r0*N + c]     = make_float2(v0+h0.x, v1+h0.y);
                    *(float2*)&Cf[(size_t)(r0+8)*N + c] = make_float2(v2+h1.x, v3+h1.y);
                }
            }
        }
    }
}

// ---------------- Attention: tensor-core, windowed causal ----------------
#define QPAD 40

__global__ __launch_bounds__(128) void attn_mma() {
    __shared__ __nv_bfloat16 Qs[64*QPAD];
    __shared__ __nv_bfloat16 Ks[128*QPAD];
    __shared__ __nv_bfloat16 Vs[128*QPAD];   // row-major [key][hd]
    const int qtile = blockIdx.x, h = blockIdx.y, s = blockIdx.z;
    const int q0 = qtile*64;
    const int tid = threadIdx.x, warp = tid>>5, lane = tid&31;

    for (int i = tid; i < 64*4; i += 128) {
        int r = i>>2, c4 = (i&3)*8;
        *(uint4*)&Qs[r*QPAD + c4] =
            *(const uint4*)&g_QKo[(size_t)(s*Tc + q0 + r)*(2*Dc) + h*HDc + c4];
    }
    for (int i = tid; i < 128*4; i += 128) {
        int r = i>>2, c4 = (i&3)*8;
        int kt = q0 - 64 + r;
        uint4 kval = make_uint4(0,0,0,0), vval = make_uint4(0,0,0,0);
        if (kt >= 0) {
            kval = *(const uint4*)&g_QKo[(size_t)(s*Tc + kt)*(2*Dc) + Dc + h*HDc + c4];
            vval = *(const uint4*)&g_Vbf[(size_t)(s*Tc + kt)*Dc + h*HDc + c4];
        }
        *(uint4*)&Ks[r*QPAD + c4] = kval;
        *(uint4*)&Vs[r*QPAD + c4] = vval;
    }
    __syncthreads();

    uint32_t aq[2][4];
    #pragma unroll
    for (int kk=0; kk<2; kk++) {
        int row = warp*16 + (lane & 15);
        int col = kk*16 + (lane >> 4)*8;
        uint32_t addr = smem_u32(&Qs[row*QPAD + col]);
        asm volatile("ldmatrix.sync.aligned.m8n8.x4.shared.b16 {%0,%1,%2,%3}, [%4];"
            : "=r"(aq[kk][0]),"=r"(aq[kk][1]),"=r"(aq[kk][2]),"=r"(aq[kk][3])
            : "r"(addr));
    }

    float sc[16][4];
    #pragma unroll
    for (int ni=0; ni<16; ni++) { sc[ni][0]=sc[ni][1]=sc[ni][2]=sc[ni][3]=0.f; }
    #pragma unroll
    for (int ni=0; ni<16; ni++) {
        #pragma unroll
        for (int kk=0; kk<2; kk++) {
            uint32_t b0, b1;
            int row = ni*8 + (lane & 7);
            int col = kk*16 + ((lane >> 3)&1)*8;
            uint32_t addr = smem_u32(&Ks[row*QPAD + col]);
            asm volatile("ldmatrix.sync.aligned.m8n8.x2.shared.b16 {%0,%1}, [%2];"
                : "=r"(b0),"=r"(b1) : "r"(addr));
            asm volatile("mma.sync.aligned.m16n8k16.row.col.f32.bf16.bf16.f32 "
                "{%0,%1,%2,%3}, {%4,%5,%6,%7}, {%8,%9}, {%0,%1,%2,%3};"
                : "+f"(sc[ni][0]),"+f"(sc[ni][1]),"+f"(sc[ni][2]),"+f"(sc[ni][3])
                : "r"(aq[kk][0]),"r"(aq[kk][1]),"r"(aq[kk][2]),"r"(aq[kk][3]),
                  "r"(b0),"r"(b1));
        }
    }

    const float scale = 0.17677669529663687f;
    const int g = lane >> 2, t4 = lane & 3;
    const int qg0 = q0 + warp*16 + g;
    const int qg1 = qg0 + 8;
    float mx0 = -INFINITY, mx1 = -INFINITY;
    #pragma unroll
    for (int ni=0; ni<16; ni++) {
        #pragma unroll
        for (int j=0; j<2; j++) {
            int col = ni*8 + 2*t4 + j;
            int kg = q0 - 64 + col;
            float v0 = sc[ni][j]   * scale;
            float v1 = sc[ni][2+j] * scale;
            bool ok0 = (kg >= 0) && (kg <= qg0) && (qg0 - kg <= WINc);
            bool ok1 = (kg >= 0) && (kg <= qg1) && (qg1 - kg <= WINc);
            sc[ni][j]   = ok0 ? v0 : -INFINITY;
            sc[ni][2+j] = ok1 ? v1 : -INFINITY;
            mx0 = fmaxf(mx0, sc[ni][j]);
            mx1 = fmaxf(mx1, sc[ni][2+j]);
        }
    }
    mx0 = fmaxf(mx0, __shfl_xor_sync(0xffffffffu, mx0, 1));
    mx0 = fmaxf(mx0, __shfl_xor_sync(0xffffffffu, mx0, 2));
    mx1 = fmaxf(mx1, __shfl_xor_sync(0xffffffffu, mx1, 1));
    mx1 = fmaxf(mx1, __shfl_xor_sync(0xffffffffu, mx1, 2));
    float sum0 = 0.f, sum1 = 0.f;
    #pragma unroll
    for (int ni=0; ni<16; ni++) {
        #pragma unroll
        for (int j=0; j<2; j++) {
            float e0 = (sc[ni][j]   > -INFINITY) ? __expf(sc[ni][j]   - mx0) : 0.f;
            float e1 = (sc[ni][2+j] > -INFINITY) ? __expf(sc[ni][2+j] - mx1) : 0.f;
            sc[ni][j] = e0; sc[ni][2+j] = e1;
            sum0 += e0; sum1 += e1;
        }
    }
    sum0 += __shfl_xor_sync(0xffffffffu, sum0, 1);
    sum0 += __shfl_xor_sync(0xffffffffu, sum0, 2);
    sum1 += __shfl_xor_sync(0xffffffffu, sum1, 1);
    sum1 += __shfl_xor_sync(0xffffffffu, sum1, 2);
    float inv0 = 1.f/sum0, inv1 = 1.f/sum1;

    uint32_t pa[8][4];
    #pragma unroll
    for (int kt8=0; kt8<8; kt8++) {
        __nv_bfloat162 t0 = __floats2bfloat162_rn(sc[2*kt8][0]*inv0,   sc[2*kt8][1]*inv0);
        __nv_bfloat162 t1 = __floats2bfloat162_rn(sc[2*kt8][2]*inv1,   sc[2*kt8][3]*inv1);
        __nv_bfloat162 t2 = __floats2bfloat162_rn(sc[2*kt8+1][0]*inv0, sc[2*kt8+1][1]*inv0);
        __nv_bfloat162 t3 = __floats2bfloat162_rn(sc[2*kt8+1][2]*inv1, sc[2*kt8+1][3]*inv1);
        pa[kt8][0] = *(uint32_t*)&t0;
        pa[kt8][1] = *(uint32_t*)&t1;
        pa[kt8][2] = *(uint32_t*)&t2;
        pa[kt8][3] = *(uint32_t*)&t3;
    }

    float oacc[4][4];
    #pragma unroll
    for (int ni=0; ni<4; ni++) { oacc[ni][0]=oacc[ni][1]=oacc[ni][2]=oacc[ni][3]=0.f; }
    #pragma unroll
    for (int kt8=0; kt8<8; kt8++) {
        #pragma unroll
        for (int ni=0; ni<4; ni++) {
            uint32_t b0, b1;
            int row = kt8*16 + ((lane >> 3)&1)*8 + (lane & 7);
            int col = ni*8;
            uint32_t addr = smem_u32(&Vs[row*QPAD + col]);
            asm volatile("ldmatrix.sync.aligned.m8n8.x2.trans.shared.b16 {%0,%1}, [%2];"
                : "=r"(b0),"=r"(b1) : "r"(addr));
            asm volatile("mma.sync.aligned.m16n8k16.row.col.f32.bf16.bf16.f32 "
                "{%0,%1,%2,%3}, {%4,%5,%6,%7}, {%8,%9}, {%0,%1,%2,%3};"
                : "+f"(oacc[ni][0]),"+f"(oacc[ni][1]),"+f"(oacc[ni][2]),"+f"(oacc[ni][3])
                : "r"(pa[kt8][0]),"r"(pa[kt8][1]),"r"(pa[kt8][2]),"r"(pa[kt8][3]),
                  "r"(b0),"r"(b1));
        }
    }

    #pragma unroll
    for (int ni=0; ni<4; ni++) {
        int col = ni*8 + 2*t4;
        __nv_bfloat162 p0 = __floats2bfloat162_rn(oacc[ni][0], oacc[ni][1]);
        __nv_bfloat162 p1 = __floats2bfloat162_rn(oacc[ni][2], oacc[ni][3]);
        *(__nv_bfloat162*)&g_Obf[(size_t)(s*Tc + qg0)*Dc + h*HDc + col] = p0;
        *(__nv_bfloat162*)&g_Obf[(size_t)(s*Tc + qg1)*Dc + h*HDc + col] = p1;
    }
}

// ---------------- K4b: LN2(h2) -> h3(bf16) ; seed ysum = sum(h2) ------------
__global__ __launch_bounds__(128) void k4b_add_ln(
        const float* __restrict__ gamma2,
        const float* __restrict__ beta2) {
    const int warp = threadIdx.x >> 5, lane = threadIdx.x & 31;
    const int row = blockIdx.x*4 + warp;
    const int d0 = lane*4;
    size_t base = (size_t)row*Dc + d0;

    float4 hc = *(const float4*)&g_y[base];   // g_y holds h2 (Wo gemm EPI 4)
    float h2[4] = {hc.x, hc.y, hc.z, hc.w};

    float tot = warp_sum(h2[0]+h2[1]+h2[2]+h2[3]);
    float mean = tot * (1.f/Dc);
    float dv[4], vs = 0.f;
    #pragma unroll
    for (int i=0;i<4;i++) { dv[i] = h2[i]-mean; vs += dv[i]*dv[i]; }
    float var = warp_sum(vs) * (1.f/Dc);
    float rstd = rsqrtf(var + 1e-5f);

    float4 g4 = *(const float4*)&gamma2[d0];
    float4 b4 = *(const float4*)&beta2[d0];
    __nv_bfloat162 hb[2];
    hb[0] = __floats2bfloat162_rn(dv[0]*rstd*g4.x + b4.x, dv[1]*rstd*g4.y + b4.y);
    hb[1] = __floats2bfloat162_rn(dv[2]*rstd*g4.z + b4.z, dv[3]*rstd*g4.w + b4.w);
    *(uint2*)&g_h3bf[base] = *(uint2*)hb;
    if (lane == 0) g_ysum[row] = tot;
}

// ---------------- K7: final combine ----------------
__global__ void k7_final(const float* __restrict__ x,
                         const float* __restrict__ W_in,
                         const float* __restrict__ b_in,
                         const float* __restrict__ W_out,
                         const float* __restrict__ b_out,
                         float* __restrict__ out) {
    __shared__ float xs[Fc];
    __shared__ float xw[Dc];
    int bt = blockIdx.x;               // b*T + t
    int tid = threadIdx.x;             // 128
    if (tid < Fc) xs[tid] = x[bt*Fc + tid];
    __syncthreads();
    float acc = b_in[tid];
    #pragma unroll
    for (int f=0; f<Fc; f++) acc += xs[f]*W_in[tid*Fc + f];
    xw[tid] = acc;
    __syncthreads();
    if (tid < Fc) {
        float yp = b_out[tid];
        for (int dd=0; dd<Dc; dd++) yp += xw[dd]*W_out[tid*Dc + dd];
        int b = bt >> 9, t = bt & (Tc-1);
        int srow = (b*Fc + tid)*Tc + t;
        float ymean = (g_ysum[srow] + g_b2sum) * (1.f/(float)Dc);
        out[bt*Fc + tid] = xs[tid] + ymean + yp;
    }
}

// ---------------- launcher ----------------
extern "C" void kernel_launch(void* const* d_in, const int* in_sizes, int n_in,
                              void* d_out, int out_size) {
    const float* x      = (const float*)d_in[0];
    const float* W_in   = (const float*)d_in[1];
    const float* b_in   = (const float*)d_in[2];
    const float* gamma1 = (const float*)d_in[3];
    const float* beta1  = (const float*)d_in[4];
    const float* gamma2 = (const float*)d_in[5];
    const float* beta2  = (const float*)d_in[6];
    const float* W_qkv  = (const float*)d_in[7];
    const float* b_qkv  = (const float*)d_in[8];
    const float* W_o    = (const float*)d_in[9];
    const float* b_o    = (const float*)d_in[10];
    const float* W1     = (const float*)d_in[11];
    const float* b1     = (const float*)d_in[12];
    const float* W2     = (const float*)d_in[13];
    const float* b2     = (const float*)d_in[14];
    const float* W_out  = (const float*)d_in[15];
    const float* b_out  = (const float*)d_in[16];
    float* out = (float*)d_out;

    float *p_hcf, *p_y, *p_ysum, *p_w2sum;
    __nv_bfloat16 *p_h1bf, *p_qkbf, *p_QKo, *p_Vbf, *p_Obf, *p_h3bf;
    __nv_bfloat16 *p_Wqkv, *p_Wo, *p_W1;
    cudaGetSymbolAddress((void**)&p_hcf,  g_hcf);
    cudaGetSymbolAddress((void**)&p_y,    g_y);
    cudaGetSymbolAddress((void**)&p_ysum, g_ysum);
    cudaGetSymbolAddress((void**)&p_w2sum,g_w2sum);
    cudaGetSymbolAddress((void**)&p_h1bf, g_h1bf);
    cudaGetSymbolAddress((void**)&p_qkbf, g_qkbf);
    cudaGetSymbolAddress((void**)&p_QKo,  g_QKo);
    cudaGetSymbolAddress((void**)&p_Vbf,  g_Vbf);
    cudaGetSymbolAddress((void**)&p_Obf,  g_Obf);
    cudaGetSymbolAddress((void**)&p_h3bf, g_h3bf);
    cudaGetSymbolAddress((void**)&p_Wqkv, g_Wqkv_bf);
    cudaGetSymbolAddress((void**)&p_Wo,   g_Wo_bf);
    cudaGetSymbolAddress((void**)&p_W1,   g_W1_bf);

    // 0) weights -> bf16 ; w2sum/b2sum
    conv_weights<<<(HIDc*Dc + 255)/256, 256>>>(W_qkv, W_o, W1, W2, b2);
    // 1) hcf + LN1 + RoPE
    k1_hcf_ln_rope<<<ROWS/4, 128>>>(x, W_in, b_in, gamma1, beta1);
    // 2) Q,K -> bf16   (N=256)
    gemm_bf16<3><<<dim3(4, ROWS/128), 256>>>(p_qkbf, p_Wqkv, b_qkv, nullptr, p_QKo, ROWS, 256, 128, nullptr, nullptr, nullptr);
    // 3) V -> bf16     (N=128)
    gemm_bf16<3><<<dim3(2, ROWS/128), 256>>>(p_h1bf, p_Wqkv + 2*Dc*Dc, b_qkv + 2*Dc, nullptr, p_Vbf, ROWS, 128, 128, nullptr, nullptr, nullptr);
    // 4) attention
    attn_mma<<<dim3(Tc/64, NHc, Sc), 128>>>();
    // 5) h2 = O @ W_o^T + b_o + hcf  (fp32, residual fused)
    gemm_bf16<4><<<dim3(2, ROWS/128), 256>>>(p_Obf, p_Wo, b_o, p_y, nullptr, ROWS, 128, 128, nullptr, nullptr, p_hcf);
    // 6) LN2(h2) -> h3 (bf16), seed ysum = sum(h2)
    k4b_add_ln<<<ROWS/4, 128>>>(gamma2, beta2);
    // 7) FFN fused: ysum += rowsum(gelu(h3@W1^T+b1) * w2sum)   (N=512)
    gemm_bf16<1><<<dim3(8, ROWS/128), 256>>>(p_h3bf, p_W1, b1, nullptr, nullptr, ROWS, 512, 128, p_ysum, p_w2sum, nullptr);
    // 8) final combine (adds b2sum)
    k7_final<<<Bc*Tc, 128>>>(x, W_in, b_in, W_out, b_out, out);
}